// round 1
// baseline (speedup 1.0000x reference)
#include <cuda_runtime.h>
#include <math.h>

// ---------------- problem constants ----------------
#define NB      64        // batch
#define CIN     64
#define TT      512       // T
#define NN      32768     // N = B*T
#define DD      128       // D = HEADS*DIM_H
#define EE      524288    // edges
#define ETOT    557056    // E + N self loops
#define EPSB    1e-5f

typedef unsigned long long ull;

// ---------------- device scratch ----------------
__device__ float g_xl[NN * DD];
__device__ float g_xr[NN * DD];
__device__ float g_expl[ETOT * 2];
__device__ float g_z[NN * 2];
__device__ float g_gacc[NN * DD];
__device__ float g_y[NB * 512 * 128];
__device__ float g_wt[9 * 512 * 512];   // conv_w transposed to [k][i][o]
__device__ float g_wf[64 * 256];        // [C_IN][W_l | W_r]
__device__ float g_wcs[256];            // column sums of fused W
__device__ float g_bn0s[64], g_bn0t[64];
__device__ float g_bn1sum[128], g_bn1sq[128], g_bn1a[128], g_bn1c[128];
__device__ float g_bn2a[512], g_bn2c[512];

// ---------------- zero accumulators ----------------
__global__ void k_zero() {
    int i = blockIdx.x * blockDim.x + threadIdx.x;
    int stride = gridDim.x * blockDim.x;
    for (int idx = i; idx < NN * DD; idx += stride) g_gacc[idx] = 0.f;
    for (int idx = i; idx < NN * 2; idx += stride) g_z[idx] = 0.f;
    if (i < 128) { g_bn1sum[i] = 0.f; g_bn1sq[i] = 0.f; }
}

// ---------------- BN0 stats -> per-channel scale/shift ----------------
__global__ void k_bn0(const float* __restrict__ x, const float* __restrict__ g,
                      const float* __restrict__ b) {
    int c = blockIdx.x;                 // 64 channels
    const float* base = x + c * 512;
    float s = 0.f, q = 0.f;
    for (int idx = threadIdx.x; idx < 32768; idx += 256) {
        float v = base[(idx >> 9) * 32768 + (idx & 511)];
        s += v; q += v * v;
    }
    __shared__ float rs[256], rq[256];
    rs[threadIdx.x] = s; rq[threadIdx.x] = q;
    __syncthreads();
    for (int st = 128; st > 0; st >>= 1) {
        if (threadIdx.x < st) { rs[threadIdx.x] += rs[threadIdx.x + st]; rq[threadIdx.x] += rq[threadIdx.x + st]; }
        __syncthreads();
    }
    if (threadIdx.x == 0) {
        float m = rs[0] * (1.f / 32768.f);
        float var = rq[0] * (1.f / 32768.f) - m * m;
        float a = g[c] * rsqrtf(var + EPSB);
        g_bn0s[c] = a;
        g_bn0t[c] = b[c] - m * a;
    }
}

// ---------------- fuse W_l|W_r + column sums ----------------
__global__ void k_fusew(const float* __restrict__ wl, const float* __restrict__ wr) {
    int j = threadIdx.x;  // 256
    float cs = 0.f;
    for (int c = 0; c < 64; c++) {
        float w = (j < 128) ? wl[c * 128 + j] : wr[c * 128 + (j - 128)];
        g_wf[c * 256 + j] = w;
        cs += w;
    }
    g_wcs[j] = cs;
}

// ---------------- GEMM: xl/xr = BN0-folded X @ [W_l|W_r] ----------------
__global__ void k_gemm1(const float* __restrict__ x) {
    __shared__ float xs[2048];
    int row0 = blockIdx.x * 32;
    for (int i = threadIdx.x; i < 2048; i += 256) xs[i] = x[row0 * 64 + i];
    __syncthreads();
    int j = threadIdx.x;
    float acc[32];
#pragma unroll
    for (int r = 0; r < 32; r++) acc[r] = 0.f;
    for (int c = 0; c < 64; c++) {
        float w = g_wf[c * 256 + j];
#pragma unroll
        for (int r = 0; r < 32; r++) acc[r] += xs[r * 64 + c] * w;
    }
    float cs = g_wcs[j];
    float* dst = (j < 128) ? g_xl : g_xr;
    int jj = j & 127;
#pragma unroll
    for (int r = 0; r < 32; r++) {
        int n = row0 + r;
        int cin = (n >> 3) & 63;
        dst[n * 128 + jj] = g_bn0s[cin] * acc[r] + g_bn0t[cin] * cs;
    }
}

// ---------------- edge pass A: exp(logit) + denominator ----------------
__global__ void k_edgeA(const int* __restrict__ ei, const float* __restrict__ att) {
    int e = blockIdx.x * 8 + (threadIdx.x >> 5);
    if (e >= ETOT) return;
    int lane = threadIdx.x & 31;
    int src, dst;
    if (e < EE) { src = ei[e]; dst = ei[EE + e]; }
    else        { src = e - EE; dst = src; }
    float4 a = *(const float4*)(g_xl + src * 128 + lane * 4);
    float4 r = *(const float4*)(g_xr + dst * 128 + lane * 4);
    float4 av = *(const float4*)(att + lane * 4);
    float hx = a.x + r.x; hx = hx > 0.f ? hx : 0.2f * hx;
    float hy = a.y + r.y; hy = hy > 0.f ? hy : 0.2f * hy;
    float hz = a.z + r.z; hz = hz > 0.f ? hz : 0.2f * hz;
    float hw = a.w + r.w; hw = hw > 0.f ? hw : 0.2f * hw;
    float s = hx * av.x + hy * av.y + hz * av.z + hw * av.w;
    s += __shfl_xor_sync(0xffffffffu, s, 8);
    s += __shfl_xor_sync(0xffffffffu, s, 4);
    s += __shfl_xor_sync(0xffffffffu, s, 2);
    s += __shfl_xor_sync(0xffffffffu, s, 1);
    if ((lane & 15) == 0) {
        int head = lane >> 4;
        float ex = expf(s);
        g_expl[e * 2 + head] = ex;
        atomicAdd(&g_z[dst * 2 + head], ex);
    }
}

// ---------------- edge pass B: weighted scatter ----------------
__global__ void k_edgeB(const int* __restrict__ ei) {
    int e = blockIdx.x * 8 + (threadIdx.x >> 5);
    if (e >= ETOT) return;
    int lane = threadIdx.x & 31;
    int src, dst;
    if (e < EE) { src = ei[e]; dst = ei[EE + e]; }
    else        { src = e - EE; dst = src; }
    int head = lane >> 4;
    float alpha = g_expl[e * 2 + head] / g_z[dst * 2 + head];
    float4 v = *(const float4*)(g_xl + src * 128 + lane * 4);
    float* o = g_gacc + dst * 128 + lane * 4;
    atomicAdd(o + 0, alpha * v.x);
    atomicAdd(o + 1, alpha * v.y);
    atomicAdd(o + 2, alpha * v.z);
    atomicAdd(o + 3, alpha * v.w);
}

// ---------------- BN1 stats (partial) ----------------
__global__ void k_bn1p() {
    __shared__ float ssum[128], ssq[128];
    int tid = threadIdx.x;
    if (tid < 128) { ssum[tid] = 0.f; ssq[tid] = 0.f; }
    __syncthreads();
    int col = tid & 127;
    float s = 0.f, q = 0.f;
    int base = blockIdx.x * 128;   // 256 blocks x 128 rows
    for (int r = tid >> 7; r < 128; r += 2) {
        float v = g_gacc[(base + r) * 128 + col];
        s += v; q += v * v;
    }
    atomicAdd(&ssum[col], s);
    atomicAdd(&ssq[col], q);
    __syncthreads();
    if (tid < 128) {
        atomicAdd(&g_bn1sum[tid], ssum[tid]);
        atomicAdd(&g_bn1sq[tid], ssq[tid]);
    }
}

__global__ void k_bn1f(const float* __restrict__ g, const float* __restrict__ b) {
    int j = threadIdx.x;   // 128
    float m = g_bn1sum[j] * (1.f / 32768.f);
    float var = g_bn1sq[j] * (1.f / 32768.f) - m * m;
    float a = g[j] * rsqrtf(var + EPSB);
    g_bn1a[j] = a;
    g_bn1c[j] = b[j] - m * a;
}

// ---------------- xn1 = relu(BN1(gacc)) -> d_out (residual base) ----------------
__global__ void k_xn1(float* __restrict__ out) {
    int i = blockIdx.x * 1024 + threadIdx.x;
    int j = i & 127;
    float v = g_gacc[i] * g_bn1a[j] + g_bn1c[j];
    out[i] = fmaxf(v, 0.f);
}

// ---------------- transpose conv_w [o][i][k] -> [k][i][o] ----------------
__global__ void k_wt(const float* __restrict__ w) {
    int idx = blockIdx.x * 256 + threadIdx.x;   // 2359296 total
    int o = idx & 511;
    int i = (idx >> 9) & 511;
    int k = idx >> 18;
    g_wt[idx] = w[(o * 512 + i) * 9 + k];
}

// ---------------- conv GEMM (f32x2 packed FFMA) ----------------
// y[b,o,p] = sum_{i,k} w[o,i,k] * X[b, p+k-4, i],  X[b,q,i] = out[b*65536 + q*512 + i]
__global__ void __launch_bounds__(256, 2) k_conv(const float* __restrict__ xin) {
    __shared__ __align__(16) float Xs[32][137];
    __shared__ __align__(16) float Ws[32][128];
    int bb = blockIdx.y;
    int o0 = blockIdx.x * 128;
    int tid = threadIdx.x;
    int tx = tid & 15, ty = tid >> 4;
    ull acc[4][8];
#pragma unroll
    for (int u = 0; u < 4; u++)
#pragma unroll
        for (int p = 0; p < 8; p++) acc[u][p] = 0ull;
    const float* xb = xin + bb * 65536;
    for (int i0 = 0; i0 < 512; i0 += 32) {
        __syncthreads();
        // load Xs[i][q+4] for q in [-4,131], zero-padded
        for (int t = tid; t < 1088; t += 256) {
            int il4 = t & 7, qc = t >> 3;   // qc 0..135
            int q = qc - 4;
            float4 v = make_float4(0.f, 0.f, 0.f, 0.f);
            if (q >= 0 && q < 128) v = *(const float4*)(xb + q * 512 + i0 + il4 * 4);
            Xs[il4 * 4 + 0][qc] = v.x;
            Xs[il4 * 4 + 1][qc] = v.y;
            Xs[il4 * 4 + 2][qc] = v.z;
            Xs[il4 * 4 + 3][qc] = v.w;
        }
        for (int k = 0; k < 9; k++) {
            __syncthreads();
            for (int t = tid; t < 1024; t += 256) {
                int oc4 = t & 31, il = t >> 5;
                *(float4*)&Ws[il][oc4 * 4] =
                    *(const float4*)&g_wt[(k * 512 + i0 + il) * 512 + o0 + oc4 * 4];
            }
            __syncthreads();
#pragma unroll
            for (int i = 0; i < 32; i++) {
                ull w2[4];
#pragma unroll
                for (int u = 0; u < 4; u++)
                    w2[u] = *(const ull*)&Ws[i][ty * 8 + u * 2];
                ull xx[8];
#pragma unroll
                for (int p = 0; p < 8; p++) {
                    float xv = Xs[i][tx + p * 16 + k];
                    asm("mov.b64 %0, {%1, %1};" : "=l"(xx[p]) : "f"(xv));
                }
#pragma unroll
                for (int u = 0; u < 4; u++)
#pragma unroll
                    for (int p = 0; p < 8; p++)
                        asm("fma.rn.f32x2 %0, %1, %2, %0;"
                            : "+l"(acc[u][p]) : "l"(w2[u]), "l"(xx[p]));
            }
        }
    }
    // epilogue -> g_y[b][o][p]  (conv bias cancels in BN2)
#pragma unroll
    for (int u = 0; u < 4; u++) {
        int o = o0 + ty * 8 + u * 2;
#pragma unroll
        for (int p = 0; p < 8; p++) {
            int pp = tx + p * 16;
            float lo, hi;
            asm("mov.b64 {%0, %1}, %2;" : "=f"(lo), "=f"(hi) : "l"(acc[u][p]));
            g_y[(bb * 512 + o) * 128 + pp] = lo;
            g_y[(bb * 512 + o + 1) * 128 + pp] = hi;
        }
    }
}

// ---------------- BN2 stats per out-channel ----------------
__global__ void k_bn2(const float* __restrict__ g, const float* __restrict__ b) {
    int o = blockIdx.x;   // 512
    float s = 0.f, q = 0.f;
    for (int idx = threadIdx.x; idx < 8192; idx += 256) {
        int bb = idx >> 7, p = idx & 127;
        float v = g_y[(bb * 512 + o) * 128 + p];
        s += v; q += v * v;
    }
    __shared__ float rs[256], rq[256];
    rs[threadIdx.x] = s; rq[threadIdx.x] = q;
    __syncthreads();
    for (int st = 128; st > 0; st >>= 1) {
        if (threadIdx.x < st) { rs[threadIdx.x] += rs[threadIdx.x + st]; rq[threadIdx.x] += rq[threadIdx.x + st]; }
        __syncthreads();
    }
    if (threadIdx.x == 0) {
        float m = rs[0] * (1.f / 8192.f);
        float var = rq[0] * (1.f / 8192.f) - m * m;
        float a = g[o] * rsqrtf(var + EPSB);
        g_bn2a[o] = a;
        g_bn2c[o] = b[o] - m * a;
    }
}

// ---------------- final: out[b,d,t] += relu(BN2(y))[b,t,d] ----------------
__global__ void k_final(float* __restrict__ out) {
    __shared__ float sh[32][33];
    int bb = blockIdx.z;
    int o0 = blockIdx.y * 32;
    int p0 = blockIdx.x * 32;
    for (int t = threadIdx.x; t < 1024; t += 256) {
        int r = t >> 5, c = t & 31;          // r = o offset, c = p offset
        int o = o0 + r;
        float v = g_y[(bb * 512 + o) * 128 + p0 + c];
        v = v * g_bn2a[o] + g_bn2c[o];
        sh[r][c] = fmaxf(v, 0.f);
    }
    __syncthreads();
    for (int t = threadIdx.x; t < 1024; t += 256) {
        int r = t >> 5, c = t & 31;          // r = d offset, c = t offset
        int d = p0 + r, tt = o0 + c;
        int idx = bb * 65536 + d * 512 + tt;
        out[idx] += sh[c][r];
    }
}

// ---------------- launch ----------------
extern "C" void kernel_launch(void* const* d_in, const int* in_sizes, int n_in,
                              void* d_out, int out_size) {
    const float* x     = (const float*)d_in[0];
    const int*   ei    = (const int*)d_in[1];
    const float* bn0g  = (const float*)d_in[2];
    const float* bn0b  = (const float*)d_in[3];
    const float* wl    = (const float*)d_in[4];
    const float* wr    = (const float*)d_in[5];
    const float* att   = (const float*)d_in[6];
    // d_in[7] gat_b: cancels exactly inside BN1 (per-channel constant)
    const float* bn1g  = (const float*)d_in[8];
    const float* bn1b  = (const float*)d_in[9];
    const float* convw = (const float*)d_in[10];
    // d_in[11] conv_b: cancels exactly inside BN2
    const float* bn2g  = (const float*)d_in[12];
    const float* bn2b  = (const float*)d_in[13];
    float* out = (float*)d_out;

    k_zero<<<4096, 1024>>>();
    k_bn0<<<64, 256>>>(x, bn0g, bn0b);
    k_fusew<<<1, 256>>>(wl, wr);
    k_gemm1<<<1024, 256>>>(x);
    k_edgeA<<<(ETOT + 7) / 8, 256>>>(ei, att);
    k_edgeB<<<(ETOT + 7) / 8, 256>>>(ei);
    k_bn1p<<<256, 256>>>();
    k_bn1f<<<1, 128>>>(bn1g, bn1b);
    k_xn1<<<4096, 1024>>>(out);
    k_wt<<<9216, 256>>>(convw);
    k_conv<<<dim3(4, 64), 256>>>(out);
    k_bn2<<<512, 256>>>(bn2g, bn2b);
    k_final<<<dim3(4, 16, 64), 256>>>(out);
}

// round 3
// speedup vs baseline: 1.8605x; 1.8605x over previous
#include <cuda_runtime.h>
#include <cuda_bf16.h>
#include <math.h>
#include <stdint.h>

// ---------------- problem constants ----------------
#define NB      64
#define CIN     64
#define TT      512
#define NN      32768
#define DD      128
#define EE      524288
#define ETOT    557056
#define EPSB    1e-5f

typedef unsigned long long ull;

// ---------------- device scratch ----------------
__device__ __align__(16) float g_xl[NN * DD];
__device__ __align__(16) float g_xr[NN * DD];
__device__ __align__(16) float g_expl[ETOT * 2];
__device__ __align__(16) float g_z[NN * 2];
__device__ __align__(16) float g_gacc[NN * DD];
__device__ __align__(16) float g_y[NB * 512 * 128];
__device__ __align__(16) float g_wf[64 * 256];
__device__ __align__(16) float g_wcs[256];
__device__ __align__(16) __nv_bfloat16 g_wbf_hi[9 * 512 * 512];  // [k][o][i]
__device__ __align__(16) __nv_bfloat16 g_wbf_lo[9 * 512 * 512];
__device__ __align__(16) __nv_bfloat16 g_xbf_hi[NB * 128 * 512]; // [b][q][i]
__device__ __align__(16) __nv_bfloat16 g_xbf_lo[NB * 128 * 512];
__device__ float g_bn0s[64], g_bn0t[64];
__device__ float g_bn1sum[128], g_bn1sq[128], g_bn1a[128], g_bn1c[128];
__device__ float g_bn2a[512], g_bn2c[512];

// ---------------- helpers ----------------
__device__ __forceinline__ uint32_t smem_u32(const void* p) {
    uint32_t a;
    asm("{ .reg .u64 t; cvta.to.shared.u64 t, %1; cvt.u32.u64 %0, t; }" : "=r"(a) : "l"(p));
    return a;
}
__device__ __forceinline__ void cpa16(uint32_t dst, const void* src) {
    asm volatile("cp.async.cg.shared.global [%0], [%1], 16;" :: "r"(dst), "l"(src));
}
__device__ __forceinline__ void ldsm4(uint32_t* r, uint32_t addr) {
    asm volatile("ldmatrix.sync.aligned.m8n8.x4.shared.b16 {%0,%1,%2,%3}, [%4];"
                 : "=r"(r[0]), "=r"(r[1]), "=r"(r[2]), "=r"(r[3]) : "r"(addr));
}
__device__ __forceinline__ void mma16816(float* d, const uint32_t* a, uint32_t b0, uint32_t b1) {
    asm volatile("mma.sync.aligned.m16n8k16.row.col.f32.bf16.bf16.f32 "
                 "{%0,%1,%2,%3}, {%4,%5,%6,%7}, {%8,%9}, {%0,%1,%2,%3};"
                 : "+f"(d[0]), "+f"(d[1]), "+f"(d[2]), "+f"(d[3])
                 : "r"(a[0]), "r"(a[1]), "r"(a[2]), "r"(a[3]), "r"(b0), "r"(b1));
}

// ---------------- zero accumulators ----------------
__global__ void k_zero() {
    int i = blockIdx.x * blockDim.x + threadIdx.x;
    int stride = gridDim.x * blockDim.x;
    for (int idx = i; idx < NN * DD; idx += stride) g_gacc[idx] = 0.f;
    for (int idx = i; idx < NN * 2; idx += stride) g_z[idx] = 0.f;
    if (i < 128) { g_bn1sum[i] = 0.f; g_bn1sq[i] = 0.f; }
}

// ---------------- BN0 stats ----------------
__global__ void k_bn0(const float* __restrict__ x, const float* __restrict__ g,
                      const float* __restrict__ b) {
    int c = blockIdx.x;
    const float* base = x + c * 512;
    float s = 0.f, q = 0.f;
    for (int idx = threadIdx.x; idx < 32768; idx += 256) {
        float v = base[(idx >> 9) * 32768 + (idx & 511)];
        s += v; q += v * v;
    }
    __shared__ float rs[256], rq[256];
    rs[threadIdx.x] = s; rq[threadIdx.x] = q;
    __syncthreads();
    for (int st = 128; st > 0; st >>= 1) {
        if (threadIdx.x < st) { rs[threadIdx.x] += rs[threadIdx.x + st]; rq[threadIdx.x] += rq[threadIdx.x + st]; }
        __syncthreads();
    }
    if (threadIdx.x == 0) {
        float m = rs[0] * (1.f / 32768.f);
        float var = rq[0] * (1.f / 32768.f) - m * m;
        float a = g[c] * rsqrtf(var + EPSB);
        g_bn0s[c] = a;
        g_bn0t[c] = b[c] - m * a;
    }
}

// ---------------- fuse W_l|W_r + column sums ----------------
__global__ void k_fusew(const float* __restrict__ wl, const float* __restrict__ wr) {
    int j = threadIdx.x;
    float cs = 0.f;
    for (int c = 0; c < 64; c++) {
        float w = (j < 128) ? wl[c * 128 + j] : wr[c * 128 + (j - 128)];
        g_wf[c * 256 + j] = w;
        cs += w;
    }
    g_wcs[j] = cs;
}

// ---------------- GEMM1: 8 rows x 8 cols per thread, f32x2 ----------------
__global__ void __launch_bounds__(256) k_gemm1(const float* __restrict__ x) {
    extern __shared__ float sm1[];
    float* xs = sm1;            // [64][64]
    float* ws = sm1 + 4096;     // [64][256]
    int tid = threadIdx.x;
    int r0 = blockIdx.x * 64;
    for (int i = tid; i < 4096; i += 256) xs[i] = x[r0 * 64 + i];
    for (int i = tid; i < 16384; i += 256) ws[i] = g_wf[i];
    __syncthreads();
    int cg = tid & 31, rg = tid >> 5;
    int j0 = cg * 8;
    ull acc[8][4];
#pragma unroll
    for (int rr = 0; rr < 8; rr++)
#pragma unroll
        for (int u = 0; u < 4; u++) acc[rr][u] = 0ull;
    for (int c = 0; c < 64; c++) {
        ull w2[4];
#pragma unroll
        for (int u = 0; u < 4; u++) w2[u] = *(const ull*)&ws[c * 256 + j0 + 2 * u];
#pragma unroll
        for (int rr = 0; rr < 8; rr++) {
            float xv = xs[(rg * 8 + rr) * 64 + c];
            ull xd;
            asm("mov.b64 %0, {%1, %1};" : "=l"(xd) : "f"(xv));
#pragma unroll
            for (int u = 0; u < 4; u++)
                asm("fma.rn.f32x2 %0, %1, %2, %0;" : "+l"(acc[rr][u]) : "l"(xd), "l"(w2[u]));
        }
    }
    float wcs[8];
#pragma unroll
    for (int u = 0; u < 8; u++) wcs[u] = g_wcs[j0 + u];
    float* dst = (j0 < 128) ? g_xl : g_xr;
    int jj = j0 & 127;
#pragma unroll
    for (int rr = 0; rr < 8; rr++) {
        int n = r0 + rg * 8 + rr;
        int cin = (n >> 3) & 63;
        float s = g_bn0s[cin], t = g_bn0t[cin];
#pragma unroll
        for (int u = 0; u < 4; u++) {
            float a0, a1;
            asm("mov.b64 {%0, %1}, %2;" : "=f"(a0), "=f"(a1) : "l"(acc[rr][u]));
            float2 v;
            v.x = s * a0 + t * wcs[2 * u];
            v.y = s * a1 + t * wcs[2 * u + 1];
            *(float2*)&dst[n * 128 + jj + 2 * u] = v;
        }
    }
}

// ---------------- edge pass A ----------------
__global__ void k_edgeA(const int* __restrict__ ei, const float* __restrict__ att) {
    int e = blockIdx.x * 8 + (threadIdx.x >> 5);
    if (e >= ETOT) return;
    int lane = threadIdx.x & 31;
    int src, dst;
    if (e < EE) { src = ei[e]; dst = ei[EE + e]; }
    else        { src = e - EE; dst = src; }
    float4 a = *(const float4*)(g_xl + src * 128 + lane * 4);
    float4 r = *(const float4*)(g_xr + dst * 128 + lane * 4);
    float4 av = *(const float4*)(att + lane * 4);
    float hx = a.x + r.x; hx = hx > 0.f ? hx : 0.2f * hx;
    float hy = a.y + r.y; hy = hy > 0.f ? hy : 0.2f * hy;
    float hz = a.z + r.z; hz = hz > 0.f ? hz : 0.2f * hz;
    float hw = a.w + r.w; hw = hw > 0.f ? hw : 0.2f * hw;
    float s = hx * av.x + hy * av.y + hz * av.z + hw * av.w;
    s += __shfl_xor_sync(0xffffffffu, s, 8);
    s += __shfl_xor_sync(0xffffffffu, s, 4);
    s += __shfl_xor_sync(0xffffffffu, s, 2);
    s += __shfl_xor_sync(0xffffffffu, s, 1);
    if ((lane & 15) == 0) {
        int head = lane >> 4;
        float ex = expf(s);
        g_expl[e * 2 + head] = ex;
        atomicAdd(&g_z[dst * 2 + head], ex);
    }
}

// ---------------- edge pass B ----------------
__global__ void k_edgeB(const int* __restrict__ ei) {
    int e = blockIdx.x * 8 + (threadIdx.x >> 5);
    if (e >= ETOT) return;
    int lane = threadIdx.x & 31;
    int src, dst;
    if (e < EE) { src = ei[e]; dst = ei[EE + e]; }
    else        { src = e - EE; dst = src; }
    int head = lane >> 4;
    float alpha = g_expl[e * 2 + head] / g_z[dst * 2 + head];
    float4 v = *(const float4*)(g_xl + src * 128 + lane * 4);
    float* o = g_gacc + dst * 128 + lane * 4;
    atomicAdd(o + 0, alpha * v.x);
    atomicAdd(o + 1, alpha * v.y);
    atomicAdd(o + 2, alpha * v.z);
    atomicAdd(o + 3, alpha * v.w);
}

// ---------------- BN1 ----------------
__global__ void k_bn1p() {
    __shared__ float ssum[128], ssq[128];
    int tid = threadIdx.x;
    if (tid < 128) { ssum[tid] = 0.f; ssq[tid] = 0.f; }
    __syncthreads();
    int col = tid & 127;
    float s = 0.f, q = 0.f;
    int base = blockIdx.x * 128;
    for (int r = tid >> 7; r < 128; r += 2) {
        float v = g_gacc[(base + r) * 128 + col];
        s += v; q += v * v;
    }
    atomicAdd(&ssum[col], s);
    atomicAdd(&ssq[col], q);
    __syncthreads();
    if (tid < 128) {
        atomicAdd(&g_bn1sum[tid], ssum[tid]);
        atomicAdd(&g_bn1sq[tid], ssq[tid]);
    }
}

__global__ void k_bn1f(const float* __restrict__ g, const float* __restrict__ b) {
    int j = threadIdx.x;
    float m = g_bn1sum[j] * (1.f / 32768.f);
    float var = g_bn1sq[j] * (1.f / 32768.f) - m * m;
    float a = g[j] * rsqrtf(var + EPSB);
    g_bn1a[j] = a;
    g_bn1c[j] = b[j] - m * a;
}

__global__ void k_xn1(float* __restrict__ out) {
    int i = blockIdx.x * 1024 + threadIdx.x;
    int j = i & 127;
    float v = g_gacc[i] * g_bn1a[j] + g_bn1c[j];
    out[i] = fmaxf(v, 0.f);
}

// ---------------- bf16 splits ----------------
__global__ void k_wsplit(const float* __restrict__ w) {
    int idx = blockIdx.x * 256 + threadIdx.x;   // [k][o][i]
    int i = idx & 511;
    int o = (idx >> 9) & 511;
    int k = idx >> 18;
    float v = w[(o * 512 + i) * 9 + k];
    __nv_bfloat16 h = __float2bfloat16(v);
    g_wbf_hi[idx] = h;
    g_wbf_lo[idx] = __float2bfloat16(v - __bfloat162float(h));
}

__global__ void k_xsplit(const float* __restrict__ xin) {
    int idx = blockIdx.x * 1024 + threadIdx.x;
    float v = xin[idx];
    __nv_bfloat16 h = __float2bfloat16(v);
    g_xbf_hi[idx] = h;
    g_xbf_lo[idx] = __float2bfloat16(v - __bfloat162float(h));
}

// ---------------- conv via mma.sync bf16x3 ----------------
// CTA: batch b, o-tile 128, p full 128. 72 steps of (i-chunk 64, k).
// smem: W stages 3x32KB @0, X buffers 2x34816 @98304. total 167936.
#define W_STAGE 32768
#define X_BASE  98304
#define X_BUF   34816

__device__ __forceinline__ void fillW(uint32_t sb, int st, int t, int o0, int tid) {
    int kk = t % 9;
    int i0 = (t / 9) * 64;
#pragma unroll
    for (int j = 0; j < 8; j++) {
        int ch = tid + j * 256;       // 2048 = 2 splits x 128 rows x 8 c
        int h = ch >> 10;
        int r = (ch >> 3) & 127;
        int c = ch & 7;
        uint32_t dst = sb + st * W_STAGE + h * 16384 + r * 128 + ((c * 16) ^ ((r & 7) * 16));
        const __nv_bfloat16* src = (h ? g_wbf_lo : g_wbf_hi)
            + (size_t)(kk * 512 + o0 + r) * 512 + i0 + c * 8;
        cpa16(dst, src);
    }
}

__device__ __forceinline__ void fillX(char* cs, uint32_t sb, int jch, int b, int tid) {
    int buf = jch & 1;
    int i0 = jch * 64;
#pragma unroll
    for (int jj = 0; jj < 9; jj++) {
        int ch = tid + jj * 256;
        if (ch < 2176) {              // 2 splits x 136 rows x 8 c
            int h = (ch >= 1088) ? 1 : 0;
            int ca = ch - h * 1088;
            int r = ca >> 3;          // 0..135
            int c = ca & 7;
            uint32_t rel = X_BASE + buf * X_BUF + h * 17408 + r * 128 + ((c * 16) ^ ((r & 7) * 16));
            int q = r - 4;
            if ((unsigned)q < 128u) {
                const __nv_bfloat16* src = (h ? g_xbf_lo : g_xbf_hi)
                    + (size_t)(b * 128 + q) * 512 + i0 + c * 8;
                cpa16(sb + rel, src);
            } else {
                *(uint4*)(cs + rel) = make_uint4(0u, 0u, 0u, 0u);
            }
        }
    }
}

__global__ void __launch_bounds__(256, 1) k_conv_hmma() {
    extern __shared__ char cs[];
    uint32_t sb = smem_u32(cs);
    const int tid = threadIdx.x;
    const int lane = tid & 31;
    const int wid = tid >> 5;
    const int wm = wid & 3;          // 4 M-warps of 32 rows
    const int wn = wid >> 2;         // 2 N-warps of 64 cols
    const int b = blockIdx.x;
    const int o0 = blockIdx.y * 128;

    float acc[2][8][4];
#pragma unroll
    for (int mt = 0; mt < 2; mt++)
#pragma unroll
        for (int nt = 0; nt < 8; nt++)
#pragma unroll
            for (int u = 0; u < 4; u++) acc[mt][nt][u] = 0.f;

    // prologue: C0 = W0 + X0, C1 = W1, C2 = W2
    fillW(sb, 0, 0, o0, tid);
    fillX(cs, sb, 0, b, tid);
    asm volatile("cp.async.commit_group;" ::: "memory");
    fillW(sb, 1, 1, o0, tid);
    asm volatile("cp.async.commit_group;" ::: "memory");
    fillW(sb, 2, 2, o0, tid);
    asm volatile("cp.async.commit_group;" ::: "memory");

    const int arow = wm * 32 + (lane & 15);
    const int aswz = (arow & 7) * 16;
    const int brow0 = wn * 64 + (lane & 15);

    for (int t = 0; t < 72; t++) {
        if (t < 70)      asm volatile("cp.async.wait_group 2;" ::: "memory");
        else if (t == 70) asm volatile("cp.async.wait_group 1;" ::: "memory");
        else              asm volatile("cp.async.wait_group 0;" ::: "memory");
        __syncthreads();

        const int st = t % 3;
        const int kk = t % 9;
        const int xb = (t / 9) & 1;
        const uint32_t wbase = sb + st * W_STAGE;
        const uint32_t xbase = sb + X_BASE + xb * X_BUF;
        const int brow = brow0 + kk;
        const int bswz = (brow & 7) * 16;

#pragma unroll
        for (int s = 0; s < 4; s++) {
            const int c16 = s * 2 + (lane >> 4);
            uint32_t afr[2][2][4];
#pragma unroll
            for (int h = 0; h < 2; h++)
#pragma unroll
                for (int mt = 0; mt < 2; mt++) {
                    uint32_t addr = wbase + h * 16384 + mt * 2048
                                  + arow * 128 + ((c16 * 16) ^ aswz);
                    ldsm4(afr[h][mt], addr);
                }
            uint32_t bfr[2][4][4];
#pragma unroll
            for (int h = 0; h < 2; h++)
#pragma unroll
                for (int n16 = 0; n16 < 4; n16++) {
                    uint32_t addr = xbase + h * 17408 + (brow + n16 * 16) * 128
                                  + ((c16 * 16) ^ bswz);
                    ldsm4(bfr[h][n16], addr);
                }
#pragma unroll
            for (int mt = 0; mt < 2; mt++)
#pragma unroll
                for (int nt = 0; nt < 8; nt++) {
                    const int n16 = nt >> 1, odd = nt & 1;
                    uint32_t b0h = bfr[0][n16][odd], b1h = bfr[0][n16][odd + 2];
                    uint32_t b0l = bfr[1][n16][odd], b1l = bfr[1][n16][odd + 2];
                    mma16816(acc[mt][nt], afr[0][mt], b0h, b1h);  // hi*hi
                    mma16816(acc[mt][nt], afr[0][mt], b0l, b1l);  // hi*lo
                    mma16816(acc[mt][nt], afr[1][mt], b0h, b1h);  // lo*hi
                }
        }
        __syncthreads();

        const int tf = t + 3;
        if (tf < 72) {
            fillW(sb, tf % 3, tf, o0, tid);
            if (tf % 9 == 0) fillX(cs, sb, tf / 9, b, tid);
            asm volatile("cp.async.commit_group;" ::: "memory");
        }
    }

    // epilogue: write g_y[b][o][p]
#pragma unroll
    for (int mt = 0; mt < 2; mt++)
#pragma unroll
        for (int nt = 0; nt < 8; nt++) {
            int o = o0 + wm * 32 + mt * 16 + (lane >> 2);
            int p = wn * 64 + nt * 8 + (lane & 3) * 2;
            float2 v0 = make_float2(acc[mt][nt][0], acc[mt][nt][1]);
            float2 v1 = make_float2(acc[mt][nt][2], acc[mt][nt][3]);
            *(float2*)&g_y[((size_t)b * 512 + o) * 128 + p] = v0;
            *(float2*)&g_y[((size_t)b * 512 + o + 8) * 128 + p] = v1;
        }
}

// ---------------- BN2 stats ----------------
__global__ void k_bn2(const float* __restrict__ g, const float* __restrict__ b) {
    int o = blockIdx.x;
    float s = 0.f, q = 0.f;
    for (int idx = threadIdx.x; idx < 8192; idx += 256) {
        int bb = idx >> 7, p = idx & 127;
        float v = g_y[(bb * 512 + o) * 128 + p];
        s += v; q += v * v;
    }
    __shared__ float rs[256], rq[256];
    rs[threadIdx.x] = s; rq[threadIdx.x] = q;
    __syncthreads();
    for (int st = 128; st > 0; st >>= 1) {
        if (threadIdx.x < st) { rs[threadIdx.x] += rs[threadIdx.x + st]; rq[threadIdx.x] += rq[threadIdx.x + st]; }
        __syncthreads();
    }
    if (threadIdx.x == 0) {
        float m = rs[0] * (1.f / 8192.f);
        float var = rq[0] * (1.f / 8192.f) - m * m;
        float a = g[o] * rsqrtf(var + EPSB);
        g_bn2a[o] = a;
        g_bn2c[o] = b[o] - m * a;
    }
}

// ---------------- final ----------------
__global__ void k_final(float* __restrict__ out) {
    __shared__ float sh[32][33];
    int bb = blockIdx.z;
    int o0 = blockIdx.y * 32;
    int p0 = blockIdx.x * 32;
    for (int t = threadIdx.x; t < 1024; t += 256) {
        int r = t >> 5, c = t & 31;
        int o = o0 + r;
        float v = g_y[(bb * 512 + o) * 128 + p0 + c];
        v = v * g_bn2a[o] + g_bn2c[o];
        sh[r][c] = fmaxf(v, 0.f);
    }
    __syncthreads();
    for (int t = threadIdx.x; t < 1024; t += 256) {
        int r = t >> 5, c = t & 31;
        int d = p0 + r, tt = o0 + c;
        int idx = bb * 65536 + d * 512 + tt;
        out[idx] += sh[c][r];
    }
}

// ---------------- launch ----------------
extern "C" void kernel_launch(void* const* d_in, const int* in_sizes, int n_in,
                              void* d_out, int out_size) {
    const float* x     = (const float*)d_in[0];
    const int*   ei    = (const int*)d_in[1];
    const float* bn0g  = (const float*)d_in[2];
    const float* bn0b  = (const float*)d_in[3];
    const float* wl    = (const float*)d_in[4];
    const float* wr    = (const float*)d_in[5];
    const float* att   = (const float*)d_in[6];
    const float* bn1g  = (const float*)d_in[8];
    const float* bn1b  = (const float*)d_in[9];
    const float* convw = (const float*)d_in[10];
    const float* bn2g  = (const float*)d_in[12];
    const float* bn2b  = (const float*)d_in[13];
    float* out = (float*)d_out;

    cudaFuncSetAttribute(k_gemm1, cudaFuncAttributeMaxDynamicSharedMemorySize, 81920);
    cudaFuncSetAttribute(k_conv_hmma, cudaFuncAttributeMaxDynamicSharedMemorySize, 167936);

    k_zero<<<4096, 1024>>>();
    k_bn0<<<64, 256>>>(x, bn0g, bn0b);
    k_fusew<<<1, 256>>>(wl, wr);
    k_wsplit<<<9216, 256>>>(convw);
    k_gemm1<<<512, 256, 81920>>>(x);
    k_edgeA<<<(ETOT + 7) / 8, 256>>>(ei, att);
    k_edgeB<<<(ETOT + 7) / 8, 256>>>(ei);
    k_bn1p<<<256, 256>>>();
    k_bn1f<<<1, 128>>>(bn1g, bn1b);
    k_xn1<<<4096, 1024>>>(out);
    k_xsplit<<<4096, 1024>>>(out);
    k_conv_hmma<<<dim3(64, 4), 256, 167936>>>();
    k_bn2<<<512, 256>>>(bn2g, bn2b);
    k_final<<<dim3(4, 16, 64), 256>>>(out);
}

// round 4
// speedup vs baseline: 2.1319x; 1.1459x over previous
#include <cuda_runtime.h>
#include <cuda_bf16.h>
#include <math.h>
#include <stdint.h>

// ---------------- problem constants ----------------
#define NB      64
#define CIN     64
#define TT      512
#define NN      32768
#define DD      128
#define EE      524288
#define ETOT    557056
#define EPSB    1e-5f

typedef unsigned long long ull;

// ---------------- device scratch ----------------
__device__ __align__(16) float g_xl[NN * DD];
__device__ __align__(16) float g_xr[NN * DD];
__device__ __align__(16) float g_gacc[NN * DD];
__device__ __align__(16) float g_y[NB * 512 * 128];
__device__ __align__(16) float g_wf[64 * 256];
__device__ __align__(16) float g_wcs[256];
__device__ __align__(16) __nv_bfloat16 g_wbf_hi[9 * 512 * 512];  // [k][o][i]
__device__ __align__(16) __nv_bfloat16 g_wbf_lo[9 * 512 * 512];
__device__ __align__(16) __nv_bfloat16 g_xbf_hi[NB * 128 * 512]; // [b][q][i]
__device__ __align__(16) __nv_bfloat16 g_xbf_lo[NB * 128 * 512];
__device__ int g_deg[NN];
__device__ int g_rowptr[NN + 1];
__device__ int g_cursor[NN];
__device__ int g_csrc[ETOT];
__device__ float g_bn0s[64], g_bn0t[64];
__device__ float g_bn1sum[128], g_bn1sq[128], g_bn1a[128], g_bn1c[128];
__device__ float g_bn2a[512], g_bn2c[512];

// ---------------- helpers ----------------
__device__ __forceinline__ uint32_t smem_u32(const void* p) {
    uint32_t a;
    asm("{ .reg .u64 t; cvta.to.shared.u64 t, %1; cvt.u32.u64 %0, t; }" : "=r"(a) : "l"(p));
    return a;
}
__device__ __forceinline__ void cpa16(uint32_t dst, const void* src) {
    asm volatile("cp.async.cg.shared.global [%0], [%1], 16;" :: "r"(dst), "l"(src));
}
__device__ __forceinline__ void ldsm4(uint32_t* r, uint32_t addr) {
    asm volatile("ldmatrix.sync.aligned.m8n8.x4.shared.b16 {%0,%1,%2,%3}, [%4];"
                 : "=r"(r[0]), "=r"(r[1]), "=r"(r[2]), "=r"(r[3]) : "r"(addr));
}
__device__ __forceinline__ void mma16816(float* d, const uint32_t* a, uint32_t b0, uint32_t b1) {
    asm volatile("mma.sync.aligned.m16n8k16.row.col.f32.bf16.bf16.f32 "
                 "{%0,%1,%2,%3}, {%4,%5,%6,%7}, {%8,%9}, {%0,%1,%2,%3};"
                 : "+f"(d[0]), "+f"(d[1]), "+f"(d[2]), "+f"(d[3])
                 : "r"(a[0]), "r"(a[1]), "r"(a[2]), "r"(a[3]), "r"(b0), "r"(b1));
}

// ---------------- tiny zero (bn1 partials only) ----------------
__global__ void k_zero2() {
    int i = threadIdx.x;
    if (i < 128) { g_bn1sum[i] = 0.f; g_bn1sq[i] = 0.f; }
}

// ---------------- CSR build ----------------
__global__ void k_deg1() {
    int n = blockIdx.x * 1024 + threadIdx.x;
    g_deg[n] = 1;   // self loop
}

__global__ void k_hist(const int* __restrict__ ei) {
    int e = blockIdx.x * 1024 + threadIdx.x;
    if (e < EE) atomicAdd(&g_deg[ei[EE + e]], 1);
}

__global__ void k_scan() {
    __shared__ int ps[1024];
    int t = threadIdx.x;
    int base = t * 32;
    int sum = 0;
    for (int i = 0; i < 32; i++) sum += g_deg[base + i];
    ps[t] = sum;
    __syncthreads();
    for (int off = 1; off < 1024; off <<= 1) {
        int v = (t >= off) ? ps[t - off] : 0;
        __syncthreads();
        ps[t] += v;
        __syncthreads();
    }
    int run = (t == 0) ? 0 : ps[t - 1];
    for (int i = 0; i < 32; i++) {
        int n = base + i;
        int d = g_deg[n];
        g_rowptr[n] = run;
        g_cursor[n] = run + 1;   // slot 0 = self loop
        g_csrc[run] = n;
        run += d;
    }
    if (t == 1023) g_rowptr[NN] = run;
}

__global__ void k_scatter(const int* __restrict__ ei) {
    int e = blockIdx.x * 1024 + threadIdx.x;
    if (e < EE) {
        int d = ei[EE + e];
        int pos = atomicAdd(&g_cursor[d], 1);
        g_csrc[pos] = ei[e];
    }
}

// ---------------- BN0 stats ----------------
__global__ void k_bn0(const float* __restrict__ x, const float* __restrict__ g,
                      const float* __restrict__ b) {
    int c = blockIdx.x;
    const float* base = x + c * 512;
    float s = 0.f, q = 0.f;
    for (int idx = threadIdx.x; idx < 32768; idx += 256) {
        float v = base[(idx >> 9) * 32768 + (idx & 511)];
        s += v; q += v * v;
    }
    __shared__ float rs[256], rq[256];
    rs[threadIdx.x] = s; rq[threadIdx.x] = q;
    __syncthreads();
    for (int st = 128; st > 0; st >>= 1) {
        if (threadIdx.x < st) { rs[threadIdx.x] += rs[threadIdx.x + st]; rq[threadIdx.x] += rq[threadIdx.x + st]; }
        __syncthreads();
    }
    if (threadIdx.x == 0) {
        float m = rs[0] * (1.f / 32768.f);
        float var = rq[0] * (1.f / 32768.f) - m * m;
        float a = g[c] * rsqrtf(var + EPSB);
        g_bn0s[c] = a;
        g_bn0t[c] = b[c] - m * a;
    }
}

// ---------------- fuse W_l|W_r + column sums ----------------
__global__ void k_fusew(const float* __restrict__ wl, const float* __restrict__ wr) {
    int j = threadIdx.x;
    float cs = 0.f;
    for (int c = 0; c < 64; c++) {
        float w = (j < 128) ? wl[c * 128 + j] : wr[c * 128 + (j - 128)];
        g_wf[c * 256 + j] = w;
        cs += w;
    }
    g_wcs[j] = cs;
}

// ---------------- GEMM1: 8 rows x 8 cols per thread, f32x2 ----------------
__global__ void __launch_bounds__(256) k_gemm1(const float* __restrict__ x) {
    extern __shared__ float sm1[];
    float* xs = sm1;            // [64][64]
    float* ws = sm1 + 4096;     // [64][256]
    int tid = threadIdx.x;
    int r0 = blockIdx.x * 64;
    for (int i = tid; i < 4096; i += 256) xs[i] = x[r0 * 64 + i];
    for (int i = tid; i < 16384; i += 256) ws[i] = g_wf[i];
    __syncthreads();
    int cg = tid & 31, rg = tid >> 5;
    int j0 = cg * 8;
    ull acc[8][4];
#pragma unroll
    for (int rr = 0; rr < 8; rr++)
#pragma unroll
        for (int u = 0; u < 4; u++) acc[rr][u] = 0ull;
    for (int c = 0; c < 64; c++) {
        ull w2[4];
#pragma unroll
        for (int u = 0; u < 4; u++) w2[u] = *(const ull*)&ws[c * 256 + j0 + 2 * u];
#pragma unroll
        for (int rr = 0; rr < 8; rr++) {
            float xv = xs[(rg * 8 + rr) * 64 + c];
            ull xd;
            asm("mov.b64 %0, {%1, %1};" : "=l"(xd) : "f"(xv));
#pragma unroll
            for (int u = 0; u < 4; u++)
                asm("fma.rn.f32x2 %0, %1, %2, %0;" : "+l"(acc[rr][u]) : "l"(xd), "l"(w2[u]));
        }
    }
    float wcs[8];
#pragma unroll
    for (int u = 0; u < 8; u++) wcs[u] = g_wcs[j0 + u];
    float* dst = (j0 < 128) ? g_xl : g_xr;
    int jj = j0 & 127;
#pragma unroll
    for (int rr = 0; rr < 8; rr++) {
        int n = r0 + rg * 8 + rr;
        int cin = (n >> 3) & 63;
        float s = g_bn0s[cin], t = g_bn0t[cin];
#pragma unroll
        for (int u = 0; u < 4; u++) {
            float a0, a1;
            asm("mov.b64 {%0, %1}, %2;" : "=f"(a0), "=f"(a1) : "l"(acc[rr][u]));
            float2 v;
            v.x = s * a0 + t * wcs[2 * u];
            v.y = s * a1 + t * wcs[2 * u + 1];
            *(float2*)&dst[n * 128 + jj + 2 * u] = v;
        }
    }
}

// ---------------- GATv2 gather: warp per destination node ----------------
__global__ void __launch_bounds__(256) k_gat(const float* __restrict__ att) {
    int n = blockIdx.x * 8 + (threadIdx.x >> 5);
    int lane = threadIdx.x & 31;
    int row = g_rowptr[n];
    int end = g_rowptr[n + 1];
    float4 r = *(const float4*)(g_xr + (size_t)n * 128 + lane * 4);
    float4 av = *(const float4*)(att + lane * 4);
    float4 acc = make_float4(0.f, 0.f, 0.f, 0.f);
    float z = 0.f;
    for (int base = row; base < end; base += 32) {
        int m = end - base;
        if (m > 32) m = 32;
        int s = (lane < m) ? g_csrc[base + lane] : 0;
        for (int j = 0; j < m; j++) {
            int src = __shfl_sync(0xffffffffu, s, j);
            float4 a = *(const float4*)(g_xl + (size_t)src * 128 + lane * 4);
            float hx = a.x + r.x; hx = fmaxf(hx, 0.2f * hx);
            float hy = a.y + r.y; hy = fmaxf(hy, 0.2f * hy);
            float hz = a.z + r.z; hz = fmaxf(hz, 0.2f * hz);
            float hw = a.w + r.w; hw = fmaxf(hw, 0.2f * hw);
            float d = hx * av.x + hy * av.y + hz * av.z + hw * av.w;
            d += __shfl_xor_sync(0xffffffffu, d, 8);
            d += __shfl_xor_sync(0xffffffffu, d, 4);
            d += __shfl_xor_sync(0xffffffffu, d, 2);
            d += __shfl_xor_sync(0xffffffffu, d, 1);
            float e = __expf(d);
            z += e;
            acc.x += e * a.x;
            acc.y += e * a.y;
            acc.z += e * a.z;
            acc.w += e * a.w;
        }
    }
    float inv = 1.f / z;
    float4 o = make_float4(acc.x * inv, acc.y * inv, acc.z * inv, acc.w * inv);
    *(float4*)(g_gacc + (size_t)n * 128 + lane * 4) = o;
}

// ---------------- BN1 ----------------
__global__ void k_bn1p() {
    __shared__ float ssum[128], ssq[128];
    int tid = threadIdx.x;
    if (tid < 128) { ssum[tid] = 0.f; ssq[tid] = 0.f; }
    __syncthreads();
    int col = tid & 127;
    float s = 0.f, q = 0.f;
    int base = blockIdx.x * 128;
    for (int r = tid >> 7; r < 128; r += 2) {
        float v = g_gacc[(base + r) * 128 + col];
        s += v; q += v * v;
    }
    atomicAdd(&ssum[col], s);
    atomicAdd(&ssq[col], q);
    __syncthreads();
    if (tid < 128) {
        atomicAdd(&g_bn1sum[tid], ssum[tid]);
        atomicAdd(&g_bn1sq[tid], ssq[tid]);
    }
}

__global__ void k_bn1f(const float* __restrict__ g, const float* __restrict__ b) {
    int j = threadIdx.x;
    float m = g_bn1sum[j] * (1.f / 32768.f);
    float var = g_bn1sq[j] * (1.f / 32768.f) - m * m;
    float a = g[j] * rsqrtf(var + EPSB);
    g_bn1a[j] = a;
    g_bn1c[j] = b[j] - m * a;
}

// ---------------- fused: relu(BN1) -> out + bf16 split ----------------
__global__ void k_xn1s(float* __restrict__ out) {
    int i = blockIdx.x * 1024 + threadIdx.x;
    int j = i & 127;
    float v = g_gacc[i] * g_bn1a[j] + g_bn1c[j];
    v = fmaxf(v, 0.f);
    out[i] = v;
    __nv_bfloat16 h = __float2bfloat16(v);
    g_xbf_hi[i] = h;
    g_xbf_lo[i] = __float2bfloat16(v - __bfloat162float(h));
}

// ---------------- conv weight bf16 split ----------------
__global__ void k_wsplit(const float* __restrict__ w) {
    int idx = blockIdx.x * 256 + threadIdx.x;   // [k][o][i]
    int i = idx & 511;
    int o = (idx >> 9) & 511;
    int k = idx >> 18;
    float v = w[(o * 512 + i) * 9 + k];
    __nv_bfloat16 h = __float2bfloat16(v);
    g_wbf_hi[idx] = h;
    g_wbf_lo[idx] = __float2bfloat16(v - __bfloat162float(h));
}

// ---------------- conv via mma.sync bf16x3 ----------------
#define W_STAGE 32768
#define X_BASE  98304
#define X_BUF   34816

__device__ __forceinline__ void fillW(uint32_t sb, int st, int t, int o0, int tid) {
    int kk = t % 9;
    int i0 = (t / 9) * 64;
#pragma unroll
    for (int j = 0; j < 8; j++) {
        int ch = tid + j * 256;
        int h = ch >> 10;
        int r = (ch >> 3) & 127;
        int c = ch & 7;
        uint32_t dst = sb + st * W_STAGE + h * 16384 + r * 128 + ((c * 16) ^ ((r & 7) * 16));
        const __nv_bfloat16* src = (h ? g_wbf_lo : g_wbf_hi)
            + (size_t)(kk * 512 + o0 + r) * 512 + i0 + c * 8;
        cpa16(dst, src);
    }
}

__device__ __forceinline__ void fillX(char* cs, uint32_t sb, int jch, int b, int tid) {
    int buf = jch & 1;
    int i0 = jch * 64;
#pragma unroll
    for (int jj = 0; jj < 9; jj++) {
        int ch = tid + jj * 256;
        if (ch < 2176) {
            int h = (ch >= 1088) ? 1 : 0;
            int ca = ch - h * 1088;
            int r = ca >> 3;
            int c = ca & 7;
            uint32_t rel = X_BASE + buf * X_BUF + h * 17408 + r * 128 + ((c * 16) ^ ((r & 7) * 16));
            int q = r - 4;
            if ((unsigned)q < 128u) {
                const __nv_bfloat16* src = (h ? g_xbf_lo : g_xbf_hi)
                    + (size_t)(b * 128 + q) * 512 + i0 + c * 8;
                cpa16(sb + rel, src);
            } else {
                *(uint4*)(cs + rel) = make_uint4(0u, 0u, 0u, 0u);
            }
        }
    }
}

__global__ void __launch_bounds__(256, 1) k_conv_hmma() {
    extern __shared__ char cs[];
    uint32_t sb = smem_u32(cs);
    const int tid = threadIdx.x;
    const int lane = tid & 31;
    const int wid = tid >> 5;
    const int wm = wid & 3;
    const int wn = wid >> 2;
    const int b = blockIdx.x;
    const int o0 = blockIdx.y * 128;

    float acc[2][8][4];
#pragma unroll
    for (int mt = 0; mt < 2; mt++)
#pragma unroll
        for (int nt = 0; nt < 8; nt++)
#pragma unroll
            for (int u = 0; u < 4; u++) acc[mt][nt][u] = 0.f;

    fillW(sb, 0, 0, o0, tid);
    fillX(cs, sb, 0, b, tid);
    asm volatile("cp.async.commit_group;" ::: "memory");
    fillW(sb, 1, 1, o0, tid);
    asm volatile("cp.async.commit_group;" ::: "memory");
    fillW(sb, 2, 2, o0, tid);
    asm volatile("cp.async.commit_group;" ::: "memory");

    const int arow = wm * 32 + (lane & 15);
    const int aswz = (arow & 7) * 16;
    const int brow0 = wn * 64 + (lane & 15);

    for (int t = 0; t < 72; t++) {
        if (t < 70)       asm volatile("cp.async.wait_group 2;" ::: "memory");
        else if (t == 70) asm volatile("cp.async.wait_group 1;" ::: "memory");
        else              asm volatile("cp.async.wait_group 0;" ::: "memory");
        __syncthreads();

        const int st = t % 3;
        const int kk = t % 9;
        const int xb = (t / 9) & 1;
        const uint32_t wbase = sb + st * W_STAGE;
        const uint32_t xbase = sb + X_BASE + xb * X_BUF;
        const int brow = brow0 + kk;
        const int bswz = (brow & 7) * 16;

#pragma unroll
        for (int s = 0; s < 4; s++) {
            const int c16 = s * 2 + (lane >> 4);
            uint32_t afr[2][2][4];
#pragma unroll
            for (int h = 0; h < 2; h++)
#pragma unroll
                for (int mt = 0; mt < 2; mt++) {
                    uint32_t addr = wbase + h * 16384 + mt * 2048
                                  + arow * 128 + ((c16 * 16) ^ aswz);
                    ldsm4(afr[h][mt], addr);
                }
            uint32_t bfr[2][4][4];
#pragma unroll
            for (int h = 0; h < 2; h++)
#pragma unroll
                for (int n16 = 0; n16 < 4; n16++) {
                    uint32_t addr = xbase + h * 17408 + (brow + n16 * 16) * 128
                                  + ((c16 * 16) ^ bswz);
                    ldsm4(bfr[h][n16], addr);
                }
#pragma unroll
            for (int mt = 0; mt < 2; mt++)
#pragma unroll
                for (int nt = 0; nt < 8; nt++) {
                    const int n16 = nt >> 1, odd = nt & 1;
                    uint32_t b0h = bfr[0][n16][odd], b1h = bfr[0][n16][odd + 2];
                    uint32_t b0l = bfr[1][n16][odd], b1l = bfr[1][n16][odd + 2];
                    mma16816(acc[mt][nt], afr[0][mt], b0h, b1h);
                    mma16816(acc[mt][nt], afr[0][mt], b0l, b1l);
                    mma16816(acc[mt][nt], afr[1][mt], b0h, b1h);
                }
        }
        __syncthreads();

        const int tf = t + 3;
        if (tf < 72) {
            fillW(sb, tf % 3, tf, o0, tid);
            if (tf % 9 == 0) fillX(cs, sb, tf / 9, b, tid);
            asm volatile("cp.async.commit_group;" ::: "memory");
        }
    }

#pragma unroll
    for (int mt = 0; mt < 2; mt++)
#pragma unroll
        for (int nt = 0; nt < 8; nt++) {
            int o = o0 + wm * 32 + mt * 16 + (lane >> 2);
            int p = wn * 64 + nt * 8 + (lane & 3) * 2;
            float2 v0 = make_float2(acc[mt][nt][0], acc[mt][nt][1]);
            float2 v1 = make_float2(acc[mt][nt][2], acc[mt][nt][3]);
            *(float2*)&g_y[((size_t)b * 512 + o) * 128 + p] = v0;
            *(float2*)&g_y[((size_t)b * 512 + o + 8) * 128 + p] = v1;
        }
}

// ---------------- BN2 stats ----------------
__global__ void k_bn2(const float* __restrict__ g, const float* __restrict__ b) {
    int o = blockIdx.x;
    float s = 0.f, q = 0.f;
    for (int idx = threadIdx.x; idx < 8192; idx += 256) {
        int bb = idx >> 7, p = idx & 127;
        float v = g_y[(bb * 512 + o) * 128 + p];
        s += v; q += v * v;
    }
    __shared__ float rs[256], rq[256];
    rs[threadIdx.x] = s; rq[threadIdx.x] = q;
    __syncthreads();
    for (int st = 128; st > 0; st >>= 1) {
        if (threadIdx.x < st) { rs[threadIdx.x] += rs[threadIdx.x + st]; rq[threadIdx.x] += rq[threadIdx.x + st]; }
        __syncthreads();
    }
    if (threadIdx.x == 0) {
        float m = rs[0] * (1.f / 8192.f);
        float var = rq[0] * (1.f / 8192.f) - m * m;
        float a = g[o] * rsqrtf(var + EPSB);
        g_bn2a[o] = a;
        g_bn2c[o] = b[o] - m * a;
    }
}

// ---------------- final ----------------
__global__ void k_final(float* __restrict__ out) {
    __shared__ float sh[32][33];
    int bb = blockIdx.z;
    int o0 = blockIdx.y * 32;
    int p0 = blockIdx.x * 32;
    for (int t = threadIdx.x; t < 1024; t += 256) {
        int r = t >> 5, c = t & 31;
        int o = o0 + r;
        float v = g_y[(bb * 512 + o) * 128 + p0 + c];
        v = v * g_bn2a[o] + g_bn2c[o];
        sh[r][c] = fmaxf(v, 0.f);
    }
    __syncthreads();
    for (int t = threadIdx.x; t < 1024; t += 256) {
        int r = t >> 5, c = t & 31;
        int d = p0 + r, tt = o0 + c;
        int idx = bb * 65536 + d * 512 + tt;
        out[idx] += sh[c][r];
    }
}

// ---------------- launch ----------------
extern "C" void kernel_launch(void* const* d_in, const int* in_sizes, int n_in,
                              void* d_out, int out_size) {
    const float* x     = (const float*)d_in[0];
    const int*   ei    = (const int*)d_in[1];
    const float* bn0g  = (const float*)d_in[2];
    const float* bn0b  = (const float*)d_in[3];
    const float* wl    = (const float*)d_in[4];
    const float* wr    = (const float*)d_in[5];
    const float* att   = (const float*)d_in[6];
    const float* bn1g  = (const float*)d_in[8];
    const float* bn1b  = (const float*)d_in[9];
    const float* convw = (const float*)d_in[10];
    const float* bn2g  = (const float*)d_in[12];
    const float* bn2b  = (const float*)d_in[13];
    float* out = (float*)d_out;

    cudaFuncSetAttribute(k_gemm1, cudaFuncAttributeMaxDynamicSharedMemorySize, 81920);
    cudaFuncSetAttribute(k_conv_hmma, cudaFuncAttributeMaxDynamicSharedMemorySize, 167936);

    k_zero2<<<1, 256>>>();
    k_deg1<<<32, 1024>>>();
    k_hist<<<512, 1024>>>(ei);
    k_bn0<<<64, 256>>>(x, bn0g, bn0b);
    k_fusew<<<1, 256>>>(wl, wr);
    k_wsplit<<<9216, 256>>>(convw);
    k_scan<<<1, 1024>>>();
    k_scatter<<<512, 1024>>>(ei);
    k_gemm1<<<512, 256, 81920>>>(x);
    k_gat<<<4096, 256>>>(att);
    k_bn1p<<<256, 256>>>();
    k_bn1f<<<1, 128>>>(bn1g, bn1b);
    k_xn1s<<<4096, 1024>>>(out);
    k_conv_hmma<<<dim3(64, 4), 256, 167936>>>();
    k_bn2<<<512, 256>>>(bn2g, bn2b);
    k_final<<<dim3(4, 16, 64), 256>>>(out);
}

// round 5
// speedup vs baseline: 2.7385x; 1.2845x over previous
#include <cuda_runtime.h>
#include <cuda_fp16.h>
#include <math.h>
#include <stdint.h>

// ---------------- problem constants ----------------
#define NB      64
#define CIN     64
#define TT      512
#define NN      32768
#define DD      128
#define EE      524288
#define ETOT    557056
#define EPSB    1e-5f

typedef unsigned long long ull;

// ---------------- device scratch ----------------
__device__ __align__(16) float g_xl[NN * DD];
__device__ __align__(16) float g_xr[NN * DD];
__device__ __align__(16) float g_gacc[NN * DD];
__device__ __align__(16) float g_y[NB * 512 * 128];
__device__ __align__(16) float g_wf[64 * 256];
__device__ __align__(16) float g_wcs[256];
__device__ __align__(16) __half g_wh[9 * 512 * 512];      // [k][o][i] fp16
__device__ __align__(16) __half g_xh_hi[NB * 128 * 512];  // [b][q][i]
__device__ __align__(16) __half g_xh_lo[NB * 128 * 512];
__device__ int g_deg[NN];
__device__ int g_rowptr[NN + 1];
__device__ int g_cursor[NN];
__device__ int g_csrc[ETOT];
__device__ float g_bn0sum[64], g_bn0sq[64];
__device__ float g_bn0s[64], g_bn0t[64];
__device__ float g_bn1sum[128], g_bn1sq[128], g_bn1a[128], g_bn1c[128];
__device__ float g_bn2a[512], g_bn2c[512];

// ---------------- helpers ----------------
__device__ __forceinline__ uint32_t smem_u32(const void* p) {
    uint32_t a;
    asm("{ .reg .u64 t; cvta.to.shared.u64 t, %1; cvt.u32.u64 %0, t; }" : "=r"(a) : "l"(p));
    return a;
}
__device__ __forceinline__ void cpa16(uint32_t dst, const void* src) {
    asm volatile("cp.async.cg.shared.global [%0], [%1], 16;" :: "r"(dst), "l"(src));
}
__device__ __forceinline__ void ldsm4(uint32_t* r, uint32_t addr) {
    asm volatile("ldmatrix.sync.aligned.m8n8.x4.shared.b16 {%0,%1,%2,%3}, [%4];"
                 : "=r"(r[0]), "=r"(r[1]), "=r"(r[2]), "=r"(r[3]) : "r"(addr));
}
__device__ __forceinline__ void mma16816h(float* d, const uint32_t* a, uint32_t b0, uint32_t b1) {
    asm volatile("mma.sync.aligned.m16n8k16.row.col.f32.f16.f16.f32 "
                 "{%0,%1,%2,%3}, {%4,%5,%6,%7}, {%8,%9}, {%0,%1,%2,%3};"
                 : "+f"(d[0]), "+f"(d[1]), "+f"(d[2]), "+f"(d[3])
                 : "r"(a[0]), "r"(a[1]), "r"(a[2]), "r"(a[3]), "r"(b0), "r"(b1));
}

// ---------------- init: deg=1 + zero partials ----------------
__global__ void k_init() {
    int i = blockIdx.x * 1024 + threadIdx.x;
    g_deg[i] = 1;
    if (i < 128) { g_bn1sum[i] = 0.f; g_bn1sq[i] = 0.f; }
    if (i < 64)  { g_bn0sum[i] = 0.f; g_bn0sq[i] = 0.f; }
}

__global__ void k_hist(const int* __restrict__ ei) {
    int e = blockIdx.x * 1024 + threadIdx.x;
    if (e < EE) atomicAdd(&g_deg[ei[EE + e]], 1);
}

// ---------------- BN0 partial stats: 512 blocks ----------------
__global__ void k_bn0p(const float* __restrict__ x) {
    int c = blockIdx.x >> 3;
    int sl = blockIdx.x & 7;
    const float4* base = (const float4*)(x + (size_t)(sl * 8) * 32768 + c * 512);
    int t = threadIdx.x;
    float s = 0.f, q = 0.f;
#pragma unroll
    for (int j = 0; j < 4; j++) {
        int u = t + j * 256;          // 0..1023 over [8 rows][128 f4]
        int r = u >> 7, col = u & 127;
        float4 v = base[(size_t)r * 8192 + col];
        s += v.x + v.y + v.z + v.w;
        q += v.x * v.x + v.y * v.y + v.z * v.z + v.w * v.w;
    }
    __shared__ float rs[256], rq[256];
    rs[t] = s; rq[t] = q;
    __syncthreads();
    for (int st = 128; st > 0; st >>= 1) {
        if (t < st) { rs[t] += rs[t + st]; rq[t] += rq[t + st]; }
        __syncthreads();
    }
    if (t == 0) { atomicAdd(&g_bn0sum[c], rs[0]); atomicAdd(&g_bn0sq[c], rq[0]); }
}

// ---------------- scan (CSR rowptr) ----------------
__global__ void k_scan() {
    __shared__ int ps[1024];
    int t = threadIdx.x;
    int base = t * 32;
    int sum = 0;
    for (int i = 0; i < 32; i++) sum += g_deg[base + i];
    ps[t] = sum;
    __syncthreads();
    for (int off = 1; off < 1024; off <<= 1) {
        int v = (t >= off) ? ps[t - off] : 0;
        __syncthreads();
        ps[t] += v;
        __syncthreads();
    }
    int run = (t == 0) ? 0 : ps[t - 1];
    for (int i = 0; i < 32; i++) {
        int n = base + i;
        int d = g_deg[n];
        g_rowptr[n] = run;
        g_cursor[n] = run + 1;   // slot 0 = self loop
        g_csrc[run] = n;
        run += d;
    }
    if (t == 1023) g_rowptr[NN] = run;
}

__global__ void k_scatter(const int* __restrict__ ei) {
    int e = blockIdx.x * 1024 + threadIdx.x;
    if (e < EE) {
        int d = ei[EE + e];
        int pos = atomicAdd(&g_cursor[d], 1);
        g_csrc[pos] = ei[e];
    }
}

// ---------------- fuse W_l|W_r + colsums + finalize BN0 ----------------
__global__ void k_fusew(const float* __restrict__ wl, const float* __restrict__ wr,
                        const float* __restrict__ g0, const float* __restrict__ b0) {
    int j = threadIdx.x;
    if (j < 64) {
        float m = g_bn0sum[j] * (1.f / 32768.f);
        float var = g_bn0sq[j] * (1.f / 32768.f) - m * m;
        float a = g0[j] * rsqrtf(var + EPSB);
        g_bn0s[j] = a;
        g_bn0t[j] = b0[j] - m * a;
    }
    float cs = 0.f;
    for (int c = 0; c < 64; c++) {
        float w = (j < 128) ? wl[c * 128 + j] : wr[c * 128 + (j - 128)];
        g_wf[c * 256 + j] = w;
        cs += w;
    }
    g_wcs[j] = cs;
}

// ---------------- GEMM1 ----------------
__global__ void __launch_bounds__(256) k_gemm1(const float* __restrict__ x) {
    extern __shared__ float sm1[];
    float* xs = sm1;            // [64][64]
    float* ws = sm1 + 4096;     // [64][256]
    int tid = threadIdx.x;
    int r0 = blockIdx.x * 64;
    for (int i = tid; i < 4096; i += 256) xs[i] = x[r0 * 64 + i];
    for (int i = tid; i < 16384; i += 256) ws[i] = g_wf[i];
    __syncthreads();
    int cg = tid & 31, rg = tid >> 5;
    int j0 = cg * 8;
    ull acc[8][4];
#pragma unroll
    for (int rr = 0; rr < 8; rr++)
#pragma unroll
        for (int u = 0; u < 4; u++) acc[rr][u] = 0ull;
    for (int c = 0; c < 64; c++) {
        ull w2[4];
#pragma unroll
        for (int u = 0; u < 4; u++) w2[u] = *(const ull*)&ws[c * 256 + j0 + 2 * u];
#pragma unroll
        for (int rr = 0; rr < 8; rr++) {
            float xv = xs[(rg * 8 + rr) * 64 + c];
            ull xd;
            asm("mov.b64 %0, {%1, %1};" : "=l"(xd) : "f"(xv));
#pragma unroll
            for (int u = 0; u < 4; u++)
                asm("fma.rn.f32x2 %0, %1, %2, %0;" : "+l"(acc[rr][u]) : "l"(xd), "l"(w2[u]));
        }
    }
    float wcs[8];
#pragma unroll
    for (int u = 0; u < 8; u++) wcs[u] = g_wcs[j0 + u];
    float* dst = (j0 < 128) ? g_xl : g_xr;
    int jj = j0 & 127;
#pragma unroll
    for (int rr = 0; rr < 8; rr++) {
        int n = r0 + rg * 8 + rr;
        int cin = (n >> 3) & 63;
        float s = g_bn0s[cin], t = g_bn0t[cin];
#pragma unroll
        for (int u = 0; u < 4; u++) {
            float a0, a1;
            asm("mov.b64 {%0, %1}, %2;" : "=f"(a0), "=f"(a1) : "l"(acc[rr][u]));
            float2 v;
            v.x = s * a0 + t * wcs[2 * u];
            v.y = s * a1 + t * wcs[2 * u + 1];
            *(float2*)&dst[n * 128 + jj + 2 * u] = v;
        }
    }
}

// ---------------- GATv2 gather: warp per destination node ----------------
__global__ void __launch_bounds__(256) k_gat(const float* __restrict__ att) {
    int n = blockIdx.x * 8 + (threadIdx.x >> 5);
    int lane = threadIdx.x & 31;
    int row = g_rowptr[n];
    int end = g_rowptr[n + 1];
    float4 r = *(const float4*)(g_xr + (size_t)n * 128 + lane * 4);
    float4 av = *(const float4*)(att + lane * 4);
    float4 acc = make_float4(0.f, 0.f, 0.f, 0.f);
    float z = 0.f;
    for (int base = row; base < end; base += 32) {
        int m = end - base;
        if (m > 32) m = 32;
        int s = (lane < m) ? g_csrc[base + lane] : 0;
        for (int j = 0; j < m; j++) {
            int src = __shfl_sync(0xffffffffu, s, j);
            float4 a = *(const float4*)(g_xl + (size_t)src * 128 + lane * 4);
            float hx = a.x + r.x; hx = fmaxf(hx, 0.2f * hx);
            float hy = a.y + r.y; hy = fmaxf(hy, 0.2f * hy);
            float hz = a.z + r.z; hz = fmaxf(hz, 0.2f * hz);
            float hw = a.w + r.w; hw = fmaxf(hw, 0.2f * hw);
            float d = hx * av.x + hy * av.y + hz * av.z + hw * av.w;
            d += __shfl_xor_sync(0xffffffffu, d, 8);
            d += __shfl_xor_sync(0xffffffffu, d, 4);
            d += __shfl_xor_sync(0xffffffffu, d, 2);
            d += __shfl_xor_sync(0xffffffffu, d, 1);
            float e = __expf(d);
            z += e;
            acc.x += e * a.x;
            acc.y += e * a.y;
            acc.z += e * a.z;
            acc.w += e * a.w;
        }
    }
    float inv = 1.f / z;
    float4 o = make_float4(acc.x * inv, acc.y * inv, acc.z * inv, acc.w * inv);
    *(float4*)(g_gacc + (size_t)n * 128 + lane * 4) = o;
}

// ---------------- BN1 ----------------
__global__ void k_bn1p() {
    __shared__ float ssum[128], ssq[128];
    int tid = threadIdx.x;
    if (tid < 128) { ssum[tid] = 0.f; ssq[tid] = 0.f; }
    __syncthreads();
    int col = tid & 127;
    float s = 0.f, q = 0.f;
    int base = blockIdx.x * 128;
    for (int r = tid >> 7; r < 128; r += 2) {
        float v = g_gacc[(base + r) * 128 + col];
        s += v; q += v * v;
    }
    atomicAdd(&ssum[col], s);
    atomicAdd(&ssq[col], q);
    __syncthreads();
    if (tid < 128) {
        atomicAdd(&g_bn1sum[tid], ssum[tid]);
        atomicAdd(&g_bn1sq[tid], ssq[tid]);
    }
}

__global__ void k_bn1f(const float* __restrict__ g, const float* __restrict__ b) {
    int j = threadIdx.x;
    float m = g_bn1sum[j] * (1.f / 32768.f);
    float var = g_bn1sq[j] * (1.f / 32768.f) - m * m;
    float a = g[j] * rsqrtf(var + EPSB);
    g_bn1a[j] = a;
    g_bn1c[j] = b[j] - m * a;
}

// ---------------- fused: relu(BN1) -> out + fp16 split ----------------
__global__ void k_xn1s(float* __restrict__ out) {
    int i = blockIdx.x * 1024 + threadIdx.x;
    int j = i & 127;
    float v = g_gacc[i] * g_bn1a[j] + g_bn1c[j];
    v = fmaxf(v, 0.f);
    out[i] = v;
    __half h = __float2half_rn(v);
    g_xh_hi[i] = h;
    g_xh_lo[i] = __float2half_rn(v - __half2float(h));
}

// ---------------- conv weight fp16 ----------------
__global__ void k_whalf(const float* __restrict__ w) {
    int idx = blockIdx.x * 256 + threadIdx.x;   // [k][o][i]
    int i = idx & 511;
    int o = (idx >> 9) & 511;
    int k = idx >> 18;
    g_wh[idx] = __float2half_rn(w[(o * 512 + i) * 9 + k]);
}

// ---------------- conv via mma.sync fp16 x2 ----------------
#define W_STAGE 16384
#define X_BASE  49152
#define X_BUF   34816

__device__ __forceinline__ void fillW(uint32_t sb, int st, int t, int o0, int tid) {
    int kk = t % 9;
    int i0 = (t / 9) * 64;
#pragma unroll
    for (int j = 0; j < 4; j++) {
        int ch = tid + j * 256;       // 1024 = 128 rows x 8 c
        int r = ch >> 3;
        int c = ch & 7;
        uint32_t dst = sb + st * W_STAGE + r * 128 + ((c * 16) ^ ((r & 7) * 16));
        const __half* src = g_wh + (size_t)(kk * 512 + o0 + r) * 512 + i0 + c * 8;
        cpa16(dst, src);
    }
}

__device__ __forceinline__ void fillX(char* cs, uint32_t sb, int jch, int b, int tid) {
    int buf = jch & 1;
    int i0 = jch * 64;
#pragma unroll
    for (int jj = 0; jj < 9; jj++) {
        int ch = tid + jj * 256;
        if (ch < 2176) {              // 2 splits x 136 rows x 8 c
            int h = (ch >= 1088) ? 1 : 0;
            int ca = ch - h * 1088;
            int r = ca >> 3;
            int c = ca & 7;
            uint32_t rel = X_BASE + buf * X_BUF + h * 17408 + r * 128 + ((c * 16) ^ ((r & 7) * 16));
            int q = r - 4;
            if ((unsigned)q < 128u) {
                const __half* src = (h ? g_xh_lo : g_xh_hi)
                    + (size_t)(b * 128 + q) * 512 + i0 + c * 8;
                cpa16(sb + rel, src);
            } else {
                *(uint4*)(cs + rel) = make_uint4(0u, 0u, 0u, 0u);
            }
        }
    }
}

__global__ void __launch_bounds__(256, 1) k_conv_hmma() {
    extern __shared__ char cs[];
    uint32_t sb = smem_u32(cs);
    const int tid = threadIdx.x;
    const int lane = tid & 31;
    const int wid = tid >> 5;
    const int wm = wid & 3;
    const int wn = wid >> 2;
    const int b = blockIdx.x;
    const int o0 = blockIdx.y * 128;

    float acc[2][8][4];
#pragma unroll
    for (int mt = 0; mt < 2; mt++)
#pragma unroll
        for (int nt = 0; nt < 8; nt++)
#pragma unroll
            for (int u = 0; u < 4; u++) acc[mt][nt][u] = 0.f;

    fillW(sb, 0, 0, o0, tid);
    fillX(cs, sb, 0, b, tid);
    asm volatile("cp.async.commit_group;" ::: "memory");
    fillW(sb, 1, 1, o0, tid);
    asm volatile("cp.async.commit_group;" ::: "memory");
    fillW(sb, 2, 2, o0, tid);
    asm volatile("cp.async.commit_group;" ::: "memory");

    const int arow = wm * 32 + (lane & 15);
    const int aswz = (arow & 7) * 16;
    const int brow0 = wn * 64 + (lane & 15);

    for (int t = 0; t < 72; t++) {
        if (t < 70)       asm volatile("cp.async.wait_group 2;" ::: "memory");
        else if (t == 70) asm volatile("cp.async.wait_group 1;" ::: "memory");
        else              asm volatile("cp.async.wait_group 0;" ::: "memory");
        __syncthreads();

        const int st = t % 3;
        const int kk = t % 9;
        const int xb = (t / 9) & 1;
        const uint32_t wbase = sb + st * W_STAGE;
        const uint32_t xbase = sb + X_BASE + xb * X_BUF;
        const int brow = brow0 + kk;
        const int bswz = (brow & 7) * 16;

#pragma unroll
        for (int s = 0; s < 4; s++) {
            const int c16 = s * 2 + (lane >> 4);
            uint32_t afr[2][4];
#pragma unroll
            for (int mt = 0; mt < 2; mt++) {
                uint32_t addr = wbase + mt * 2048 + arow * 128 + ((c16 * 16) ^ aswz);
                ldsm4(afr[mt], addr);
            }
            uint32_t bfr[2][4][4];
#pragma unroll
            for (int h = 0; h < 2; h++)
#pragma unroll
                for (int n16 = 0; n16 < 4; n16++) {
                    uint32_t addr = xbase + h * 17408 + (brow + n16 * 16) * 128
                                  + ((c16 * 16) ^ bswz);
                    ldsm4(bfr[h][n16], addr);
                }
#pragma unroll
            for (int mt = 0; mt < 2; mt++)
#pragma unroll
                for (int nt = 0; nt < 8; nt++) {
                    const int n16 = nt >> 1, odd = nt & 1;
                    mma16816h(acc[mt][nt], afr[mt], bfr[0][n16][odd], bfr[0][n16][odd + 2]);
                    mma16816h(acc[mt][nt], afr[mt], bfr[1][n16][odd], bfr[1][n16][odd + 2]);
                }
        }
        __syncthreads();

        const int tf = t + 3;
        if (tf < 72) {
            fillW(sb, tf % 3, tf, o0, tid);
            if (tf % 9 == 0) fillX(cs, sb, tf / 9, b, tid);
            asm volatile("cp.async.commit_group;" ::: "memory");
        }
    }

#pragma unroll
    for (int mt = 0; mt < 2; mt++)
#pragma unroll
        for (int nt = 0; nt < 8; nt++) {
            int o = o0 + wm * 32 + mt * 16 + (lane >> 2);
            int p = wn * 64 + nt * 8 + (lane & 3) * 2;
            float2 v0 = make_float2(acc[mt][nt][0], acc[mt][nt][1]);
            float2 v1 = make_float2(acc[mt][nt][2], acc[mt][nt][3]);
            *(float2*)&g_y[((size_t)b * 512 + o) * 128 + p] = v0;
            *(float2*)&g_y[((size_t)b * 512 + o + 8) * 128 + p] = v1;
        }
}

// ---------------- BN2 stats ----------------
__global__ void k_bn2(const float* __restrict__ g, const float* __restrict__ b) {
    int o = blockIdx.x;
    float s = 0.f, q = 0.f;
    for (int idx = threadIdx.x; idx < 8192; idx += 256) {
        int bb = idx >> 7, p = idx & 127;
        float v = g_y[(bb * 512 + o) * 128 + p];
        s += v; q += v * v;
    }
    __shared__ float rs[256], rq[256];
    rs[threadIdx.x] = s; rq[threadIdx.x] = q;
    __syncthreads();
    for (int st = 128; st > 0; st >>= 1) {
        if (threadIdx.x < st) { rs[threadIdx.x] += rs[threadIdx.x + st]; rq[threadIdx.x] += rq[threadIdx.x + st]; }
        __syncthreads();
    }
    if (threadIdx.x == 0) {
        float m = rs[0] * (1.f / 8192.f);
        float var = rq[0] * (1.f / 8192.f) - m * m;
        float a = g[o] * rsqrtf(var + EPSB);
        g_bn2a[o] = a;
        g_bn2c[o] = b[o] - m * a;
    }
}

// ---------------- final ----------------
__global__ void k_final(float* __restrict__ out) {
    __shared__ float sh[32][33];
    int bb = blockIdx.z;
    int o0 = blockIdx.y * 32;
    int p0 = blockIdx.x * 32;
    for (int t = threadIdx.x; t < 1024; t += 256) {
        int r = t >> 5, c = t & 31;
        int o = o0 + r;
        float v = g_y[(bb * 512 + o) * 128 + p0 + c];
        v = v * g_bn2a[o] + g_bn2c[o];
        sh[r][c] = fmaxf(v, 0.f);
    }
    __syncthreads();
    for (int t = threadIdx.x; t < 1024; t += 256) {
        int r = t >> 5, c = t & 31;
        int d = p0 + r, tt = o0 + c;
        int idx = bb * 65536 + d * 512 + tt;
        out[idx] += sh[c][r];
    }
}

// ---------------- launch ----------------
extern "C" void kernel_launch(void* const* d_in, const int* in_sizes, int n_in,
                              void* d_out, int out_size) {
    const float* x     = (const float*)d_in[0];
    const int*   ei    = (const int*)d_in[1];
    const float* bn0g  = (const float*)d_in[2];
    const float* bn0b  = (const float*)d_in[3];
    const float* wl    = (const float*)d_in[4];
    const float* wr    = (const float*)d_in[5];
    const float* att   = (const float*)d_in[6];
    const float* bn1g  = (const float*)d_in[8];
    const float* bn1b  = (const float*)d_in[9];
    const float* convw = (const float*)d_in[10];
    const float* bn2g  = (const float*)d_in[12];
    const float* bn2b  = (const float*)d_in[13];
    float* out = (float*)d_out;

    cudaFuncSetAttribute(k_gemm1, cudaFuncAttributeMaxDynamicSharedMemorySize, 81920);
    cudaFuncSetAttribute(k_conv_hmma, cudaFuncAttributeMaxDynamicSharedMemorySize, 118784);

    k_init<<<32, 1024>>>();
    k_hist<<<512, 1024>>>(ei);
    k_bn0p<<<512, 256>>>(x);
    k_scan<<<1, 1024>>>();
    k_scatter<<<512, 1024>>>(ei);
    k_fusew<<<1, 256>>>(wl, wr, bn0g, bn0b);
    k_whalf<<<9216, 256>>>(convw);
    k_gemm1<<<512, 256, 81920>>>(x);
    k_gat<<<4096, 256>>>(att);
    k_bn1p<<<256, 256>>>();
    k_bn1f<<<1, 128>>>(bn1g, bn1b);
    k_xn1s<<<4096, 1024>>>(out);
    k_conv_hmma<<<dim3(64, 4), 256, 118784>>>();
    k_bn2<<<512, 256>>>(bn2g, bn2b);
    k_final<<<dim3(4, 16, 64), 256>>>(out);
}

// round 6
// speedup vs baseline: 3.4242x; 1.2504x over previous
#include <cuda_runtime.h>
#include <cuda_fp16.h>
#include <math.h>
#include <stdint.h>

// ---------------- problem constants ----------------
#define NB      64
#define CIN     64
#define TT      512
#define NN      32768
#define DD      128
#define EE      524288
#define ETOT    557056
#define EPSB    1e-5f

typedef unsigned long long ull;

// ---------------- device scratch ----------------
__device__ __align__(16) float g_xl[NN * DD];
__device__ __align__(16) float g_xr[NN * DD];
__device__ __align__(16) float g_gacc[NN * DD];
__device__ __align__(16) float g_y[NB * 512 * 128];
__device__ __align__(16) float g_wf[64 * 256];
__device__ __align__(16) float g_wcs[256];
__device__ __align__(16) __half g_wh[9 * 512 * 512];      // [k][o][i] fp16
__device__ __align__(16) __half g_xh_hi[NB * 128 * 512];  // [b][q][i]
__device__ __align__(16) __half g_xh_lo[NB * 128 * 512];
__device__ int g_deg[NN];
__device__ int g_rowptr[NN + 1];
__device__ int g_cursor[NN];
__device__ int g_csrc[ETOT];
__device__ int g_bsum[32];
__device__ int g_boff[32];
__device__ float g_bn0sum[64], g_bn0sq[64];
__device__ float g_bn0s[64], g_bn0t[64];
__device__ float g_bn1sum[128], g_bn1sq[128], g_bn1a[128], g_bn1c[128];
__device__ float g_bn2a[512], g_bn2c[512];

// ---------------- helpers ----------------
__device__ __forceinline__ uint32_t smem_u32(const void* p) {
    uint32_t a;
    asm("{ .reg .u64 t; cvta.to.shared.u64 t, %1; cvt.u32.u64 %0, t; }" : "=r"(a) : "l"(p));
    return a;
}
__device__ __forceinline__ void cpa16(uint32_t dst, const void* src) {
    asm volatile("cp.async.cg.shared.global [%0], [%1], 16;" :: "r"(dst), "l"(src));
}
__device__ __forceinline__ void ldsm4(uint32_t* r, uint32_t addr) {
    asm volatile("ldmatrix.sync.aligned.m8n8.x4.shared.b16 {%0,%1,%2,%3}, [%4];"
                 : "=r"(r[0]), "=r"(r[1]), "=r"(r[2]), "=r"(r[3]) : "r"(addr));
}
__device__ __forceinline__ void mma16816h(float* d, const uint32_t* a, uint32_t b0, uint32_t b1) {
    asm volatile("mma.sync.aligned.m16n8k16.row.col.f32.f16.f16.f32 "
                 "{%0,%1,%2,%3}, {%4,%5,%6,%7}, {%8,%9}, {%0,%1,%2,%3};"
                 : "+f"(d[0]), "+f"(d[1]), "+f"(d[2]), "+f"(d[3])
                 : "r"(a[0]), "r"(a[1]), "r"(a[2]), "r"(a[3]), "r"(b0), "r"(b1));
}

// ---------------- init: deg=1 + zero partials ----------------
__global__ void k_init() {
    int i = blockIdx.x * 1024 + threadIdx.x;
    g_deg[i] = 1;
    if (i < 128) { g_bn1sum[i] = 0.f; g_bn1sq[i] = 0.f; }
    if (i < 64)  { g_bn0sum[i] = 0.f; g_bn0sq[i] = 0.f; }
}

__global__ void k_hist(const int* __restrict__ ei) {
    int e = blockIdx.x * 1024 + threadIdx.x;
    if (e < EE) atomicAdd(&g_deg[ei[EE + e]], 1);
}

// ---------------- BN0 partial stats ----------------
__global__ void k_bn0p(const float* __restrict__ x) {
    int c = blockIdx.x >> 3;
    int sl = blockIdx.x & 7;
    const float4* base = (const float4*)(x + (size_t)(sl * 8) * 32768 + c * 512);
    int t = threadIdx.x;
    float s = 0.f, q = 0.f;
#pragma unroll
    for (int j = 0; j < 4; j++) {
        int u = t + j * 256;
        int r = u >> 7, col = u & 127;
        float4 v = base[(size_t)r * 8192 + col];
        s += v.x + v.y + v.z + v.w;
        q += v.x * v.x + v.y * v.y + v.z * v.z + v.w * v.w;
    }
    __shared__ float rs[256], rq[256];
    rs[t] = s; rq[t] = q;
    __syncthreads();
    for (int st = 128; st > 0; st >>= 1) {
        if (t < st) { rs[t] += rs[t + st]; rq[t] += rq[t + st]; }
        __syncthreads();
    }
    if (t == 0) { atomicAdd(&g_bn0sum[c], rs[0]); atomicAdd(&g_bn0sq[c], rq[0]); }
}

// ---------------- parallel scan ----------------
__global__ void __launch_bounds__(1024) k_scanA() {
    __shared__ int wsum[32];
    int t = threadIdx.x;
    int n = blockIdx.x * 1024 + t;
    int lane = t & 31, w = t >> 5;
    int d = g_deg[n];
    // warp inclusive scan
    int incl = d;
#pragma unroll
    for (int off = 1; off < 32; off <<= 1) {
        int v = __shfl_up_sync(0xffffffffu, incl, off);
        if (lane >= off) incl += v;
    }
    if (lane == 31) wsum[w] = incl;
    __syncthreads();
    if (w == 0) {
        int v = wsum[lane];
        int wi = v;
#pragma unroll
        for (int off = 1; off < 32; off <<= 1) {
            int u = __shfl_up_sync(0xffffffffu, wi, off);
            if (lane >= off) wi += u;
        }
        wsum[lane] = wi - v;   // exclusive warp offset
        if (lane == 31) g_bsum[blockIdx.x] = wi;
    }
    __syncthreads();
    g_rowptr[n] = incl - d + wsum[w];   // block-local exclusive
}

__global__ void k_scanB() {
    int lane = threadIdx.x;   // 32
    int v = g_bsum[lane];
    int s = v;
#pragma unroll
    for (int off = 1; off < 32; off <<= 1) {
        int u = __shfl_up_sync(0xffffffffu, s, off);
        if (lane >= off) s += u;
    }
    g_boff[lane] = s - v;
    if (lane == 31) g_rowptr[NN] = s;
}

__global__ void __launch_bounds__(1024) k_scanC() {
    int n = blockIdx.x * 1024 + threadIdx.x;
    int run = g_rowptr[n] + g_boff[blockIdx.x];
    g_rowptr[n] = run;
    g_cursor[n] = run + 1;    // slot 0 = self loop
    g_csrc[run] = n;
}

__global__ void k_scatter(const int* __restrict__ ei) {
    int e = blockIdx.x * 1024 + threadIdx.x;
    if (e < EE) {
        int d = ei[EE + e];
        int pos = atomicAdd(&g_cursor[d], 1);
        g_csrc[pos] = ei[e];
    }
}

// ---------------- fuse W_l|W_r + colsums + finalize BN0 ----------------
__global__ void k_fusew(const float* __restrict__ wl, const float* __restrict__ wr,
                        const float* __restrict__ g0, const float* __restrict__ b0) {
    int j = threadIdx.x;
    if (j < 64) {
        float m = g_bn0sum[j] * (1.f / 32768.f);
        float var = g_bn0sq[j] * (1.f / 32768.f) - m * m;
        float a = g0[j] * rsqrtf(var + EPSB);
        g_bn0s[j] = a;
        g_bn0t[j] = b0[j] - m * a;
    }
    float cs = 0.f;
    for (int c = 0; c < 64; c++) {
        float w = (j < 128) ? wl[c * 128 + j] : wr[c * 128 + (j - 128)];
        g_wf[c * 256 + j] = w;
        cs += w;
    }
    g_wcs[j] = cs;
}

// ---------------- GEMM1 ----------------
__global__ void __launch_bounds__(256) k_gemm1(const float* __restrict__ x) {
    extern __shared__ float sm1[];
    float* xs = sm1;            // [64][64]
    float* ws = sm1 + 4096;     // [64][256]
    int tid = threadIdx.x;
    int r0 = blockIdx.x * 64;
    for (int i = tid; i < 4096; i += 256) xs[i] = x[r0 * 64 + i];
    for (int i = tid; i < 16384; i += 256) ws[i] = g_wf[i];
    __syncthreads();
    int cg = tid & 31, rg = tid >> 5;
    int j0 = cg * 8;
    ull acc[8][4];
#pragma unroll
    for (int rr = 0; rr < 8; rr++)
#pragma unroll
        for (int u = 0; u < 4; u++) acc[rr][u] = 0ull;
    for (int c = 0; c < 64; c++) {
        ull w2[4];
#pragma unroll
        for (int u = 0; u < 4; u++) w2[u] = *(const ull*)&ws[c * 256 + j0 + 2 * u];
#pragma unroll
        for (int rr = 0; rr < 8; rr++) {
            float xv = xs[(rg * 8 + rr) * 64 + c];
            ull xd;
            asm("mov.b64 %0, {%1, %1};" : "=l"(xd) : "f"(xv));
#pragma unroll
            for (int u = 0; u < 4; u++)
                asm("fma.rn.f32x2 %0, %1, %2, %0;" : "+l"(acc[rr][u]) : "l"(xd), "l"(w2[u]));
        }
    }
    float wcs[8];
#pragma unroll
    for (int u = 0; u < 8; u++) wcs[u] = g_wcs[j0 + u];
    float* dst = (j0 < 128) ? g_xl : g_xr;
    int jj = j0 & 127;
#pragma unroll
    for (int rr = 0; rr < 8; rr++) {
        int n = r0 + rg * 8 + rr;
        int cin = (n >> 3) & 63;
        float s = g_bn0s[cin], t = g_bn0t[cin];
#pragma unroll
        for (int u = 0; u < 4; u++) {
            float a0, a1;
            asm("mov.b64 {%0, %1}, %2;" : "=f"(a0), "=f"(a1) : "l"(acc[rr][u]));
            float2 v;
            v.x = s * a0 + t * wcs[2 * u];
            v.y = s * a1 + t * wcs[2 * u + 1];
            *(float2*)&dst[n * 128 + jj + 2 * u] = v;
        }
    }
}

// ---------------- GATv2 gather: warp per destination node ----------------
__global__ void __launch_bounds__(256) k_gat(const float* __restrict__ att) {
    int n = blockIdx.x * 8 + (threadIdx.x >> 5);
    int lane = threadIdx.x & 31;
    int row = g_rowptr[n];
    int end = g_rowptr[n + 1];
    float4 r = *(const float4*)(g_xr + (size_t)n * 128 + lane * 4);
    float4 av = *(const float4*)(att + lane * 4);
    float4 acc = make_float4(0.f, 0.f, 0.f, 0.f);
    float z = 0.f;
    for (int base = row; base < end; base += 32) {
        int m = end - base;
        if (m > 32) m = 32;
        int s = (lane < m) ? g_csrc[base + lane] : 0;
        for (int j = 0; j < m; j++) {
            int src = __shfl_sync(0xffffffffu, s, j);
            float4 a = *(const float4*)(g_xl + (size_t)src * 128 + lane * 4);
            float hx = a.x + r.x; hx = fmaxf(hx, 0.2f * hx);
            float hy = a.y + r.y; hy = fmaxf(hy, 0.2f * hy);
            float hz = a.z + r.z; hz = fmaxf(hz, 0.2f * hz);
            float hw = a.w + r.w; hw = fmaxf(hw, 0.2f * hw);
            float d = hx * av.x + hy * av.y + hz * av.z + hw * av.w;
            d += __shfl_xor_sync(0xffffffffu, d, 8);
            d += __shfl_xor_sync(0xffffffffu, d, 4);
            d += __shfl_xor_sync(0xffffffffu, d, 2);
            d += __shfl_xor_sync(0xffffffffu, d, 1);
            float e = __expf(d);
            z += e;
            acc.x += e * a.x;
            acc.y += e * a.y;
            acc.z += e * a.z;
            acc.w += e * a.w;
        }
    }
    float inv = 1.f / z;
    float4 o = make_float4(acc.x * inv, acc.y * inv, acc.z * inv, acc.w * inv);
    *(float4*)(g_gacc + (size_t)n * 128 + lane * 4) = o;
}

// ---------------- BN1 ----------------
__global__ void k_bn1p() {
    __shared__ float ssum[128], ssq[128];
    int tid = threadIdx.x;
    if (tid < 128) { ssum[tid] = 0.f; ssq[tid] = 0.f; }
    __syncthreads();
    int col = tid & 127;
    float s = 0.f, q = 0.f;
    int base = blockIdx.x * 128;
    for (int r = tid >> 7; r < 128; r += 2) {
        float v = g_gacc[(base + r) * 128 + col];
        s += v; q += v * v;
    }
    atomicAdd(&ssum[col], s);
    atomicAdd(&ssq[col], q);
    __syncthreads();
    if (tid < 128) {
        atomicAdd(&g_bn1sum[tid], ssum[tid]);
        atomicAdd(&g_bn1sq[tid], ssq[tid]);
    }
}

__global__ void k_bn1f(const float* __restrict__ g, const float* __restrict__ b) {
    int j = threadIdx.x;
    float m = g_bn1sum[j] * (1.f / 32768.f);
    float var = g_bn1sq[j] * (1.f / 32768.f) - m * m;
    float a = g[j] * rsqrtf(var + EPSB);
    g_bn1a[j] = a;
    g_bn1c[j] = b[j] - m * a;
}

// ---------------- fused: relu(BN1) -> out + fp16 split ----------------
__global__ void k_xn1s(float* __restrict__ out) {
    int i = blockIdx.x * 1024 + threadIdx.x;
    int j = i & 127;
    float v = g_gacc[i] * g_bn1a[j] + g_bn1c[j];
    v = fmaxf(v, 0.f);
    out[i] = v;
    __half h = __float2half_rn(v);
    g_xh_hi[i] = h;
    g_xh_lo[i] = __float2half_rn(v - __half2float(h));
}

// ---------------- conv weight fp16 ----------------
__global__ void k_whalf(const float* __restrict__ w) {
    int idx = blockIdx.x * 256 + threadIdx.x;   // [k][o][i]
    int i = idx & 511;
    int o = (idx >> 9) & 511;
    int k = idx >> 18;
    g_wh[idx] = __float2half_rn(w[(o * 512 + i) * 9 + k]);
}

// ---------------- conv via mma.sync fp16 x2 ----------------
#define W_STAGE 16384
#define X_BASE  49152
#define X_BUF   34816

__device__ __forceinline__ void fillW(uint32_t sb, int st, int t, int o0, int tid) {
    int kk = t % 9;
    int i0 = (t / 9) * 64;
#pragma unroll
    for (int j = 0; j < 4; j++) {
        int ch = tid + j * 256;
        int r = ch >> 3;
        int c = ch & 7;
        uint32_t dst = sb + st * W_STAGE + r * 128 + ((c * 16) ^ ((r & 7) * 16));
        const __half* src = g_wh + (size_t)(kk * 512 + o0 + r) * 512 + i0 + c * 8;
        cpa16(dst, src);
    }
}

__device__ __forceinline__ void fillX(char* cs, uint32_t sb, int jch, int b, int tid) {
    int buf = jch & 1;
    int i0 = jch * 64;
#pragma unroll
    for (int jj = 0; jj < 9; jj++) {
        int ch = tid + jj * 256;
        if (ch < 2176) {
            int h = (ch >= 1088) ? 1 : 0;
            int ca = ch - h * 1088;
            int r = ca >> 3;
            int c = ca & 7;
            uint32_t rel = X_BASE + buf * X_BUF + h * 17408 + r * 128 + ((c * 16) ^ ((r & 7) * 16));
            int q = r - 4;
            if ((unsigned)q < 128u) {
                const __half* src = (h ? g_xh_lo : g_xh_hi)
                    + (size_t)(b * 128 + q) * 512 + i0 + c * 8;
                cpa16(sb + rel, src);
            } else {
                *(uint4*)(cs + rel) = make_uint4(0u, 0u, 0u, 0u);
            }
        }
    }
}

__global__ void __launch_bounds__(256, 1) k_conv_hmma() {
    extern __shared__ char cs[];
    uint32_t sb = smem_u32(cs);
    const int tid = threadIdx.x;
    const int lane = tid & 31;
    const int wid = tid >> 5;
    const int wm = wid & 3;
    const int wn = wid >> 2;
    const int b = blockIdx.x;
    const int o0 = blockIdx.y * 128;

    float acc[2][8][4];
#pragma unroll
    for (int mt = 0; mt < 2; mt++)
#pragma unroll
        for (int nt = 0; nt < 8; nt++)
#pragma unroll
            for (int u = 0; u < 4; u++) acc[mt][nt][u] = 0.f;

    fillW(sb, 0, 0, o0, tid);
    fillX(cs, sb, 0, b, tid);
    asm volatile("cp.async.commit_group;" ::: "memory");
    fillW(sb, 1, 1, o0, tid);
    asm volatile("cp.async.commit_group;" ::: "memory");
    fillW(sb, 2, 2, o0, tid);
    asm volatile("cp.async.commit_group;" ::: "memory");

    const int arow = wm * 32 + (lane & 15);
    const int aswz = (arow & 7) * 16;
    const int brow0 = wn * 64 + (lane & 15);

    for (int t = 0; t < 72; t++) {
        if (t < 70)       asm volatile("cp.async.wait_group 2;" ::: "memory");
        else if (t == 70) asm volatile("cp.async.wait_group 1;" ::: "memory");
        else              asm volatile("cp.async.wait_group 0;" ::: "memory");
        __syncthreads();

        const int st = t % 3;
        const int kk = t % 9;
        const int xb = (t / 9) & 1;
        const uint32_t wbase = sb + st * W_STAGE;
        const uint32_t xbase = sb + X_BASE + xb * X_BUF;
        const int brow = brow0 + kk;
        const int bswz = (brow & 7) * 16;

#pragma unroll
        for (int s = 0; s < 4; s++) {
            const int c16 = s * 2 + (lane >> 4);
            uint32_t afr[2][4];
#pragma unroll
            for (int mt = 0; mt < 2; mt++) {
                uint32_t addr = wbase + mt * 2048 + arow * 128 + ((c16 * 16) ^ aswz);
                ldsm4(afr[mt], addr);
            }
            uint32_t bfr[2][4][4];
#pragma unroll
            for (int h = 0; h < 2; h++)
#pragma unroll
                for (int n16 = 0; n16 < 4; n16++) {
                    uint32_t addr = xbase + h * 17408 + (brow + n16 * 16) * 128
                                  + ((c16 * 16) ^ bswz);
                    ldsm4(bfr[h][n16], addr);
                }
#pragma unroll
            for (int mt = 0; mt < 2; mt++)
#pragma unroll
                for (int nt = 0; nt < 8; nt++) {
                    const int n16 = nt >> 1, odd = nt & 1;
                    mma16816h(acc[mt][nt], afr[mt], bfr[0][n16][odd], bfr[0][n16][odd + 2]);
                    mma16816h(acc[mt][nt], afr[mt], bfr[1][n16][odd], bfr[1][n16][odd + 2]);
                }
        }
        __syncthreads();

        const int tf = t + 3;
        if (tf < 72) {
            fillW(sb, tf % 3, tf, o0, tid);
            if (tf % 9 == 0) fillX(cs, sb, tf / 9, b, tid);
            asm volatile("cp.async.commit_group;" ::: "memory");
        }
    }

#pragma unroll
    for (int mt = 0; mt < 2; mt++)
#pragma unroll
        for (int nt = 0; nt < 8; nt++) {
            int o = o0 + wm * 32 + mt * 16 + (lane >> 2);
            int p = wn * 64 + nt * 8 + (lane & 3) * 2;
            float2 v0 = make_float2(acc[mt][nt][0], acc[mt][nt][1]);
            float2 v1 = make_float2(acc[mt][nt][2], acc[mt][nt][3]);
            *(float2*)&g_y[((size_t)b * 512 + o) * 128 + p] = v0;
            *(float2*)&g_y[((size_t)b * 512 + o + 8) * 128 + p] = v1;
        }
}

// ---------------- BN2 stats ----------------
__global__ void k_bn2(const float* __restrict__ g, const float* __restrict__ b) {
    int o = blockIdx.x;
    float s = 0.f, q = 0.f;
    for (int idx = threadIdx.x; idx < 8192; idx += 256) {
        int bb = idx >> 7, p = idx & 127;
        float v = g_y[(bb * 512 + o) * 128 + p];
        s += v; q += v * v;
    }
    __shared__ float rs[256], rq[256];
    rs[threadIdx.x] = s; rq[threadIdx.x] = q;
    __syncthreads();
    for (int st = 128; st > 0; st >>= 1) {
        if (threadIdx.x < st) { rs[threadIdx.x] += rs[threadIdx.x + st]; rq[threadIdx.x] += rq[threadIdx.x + st]; }
        __syncthreads();
    }
    if (threadIdx.x == 0) {
        float m = rs[0] * (1.f / 8192.f);
        float var = rq[0] * (1.f / 8192.f) - m * m;
        float a = g[o] * rsqrtf(var + EPSB);
        g_bn2a[o] = a;
        g_bn2c[o] = b[o] - m * a;
    }
}

// ---------------- final ----------------
__global__ void k_final(float* __restrict__ out) {
    __shared__ float sh[32][33];
    int bb = blockIdx.z;
    int o0 = blockIdx.y * 32;
    int p0 = blockIdx.x * 32;
    for (int t = threadIdx.x; t < 1024; t += 256) {
        int r = t >> 5, c = t & 31;
        int o = o0 + r;
        float v = g_y[(bb * 512 + o) * 128 + p0 + c];
        v = v * g_bn2a[o] + g_bn2c[o];
        sh[r][c] = fmaxf(v, 0.f);
    }
    __syncthreads();
    for (int t = threadIdx.x; t < 1024; t += 256) {
        int r = t >> 5, c = t & 31;
        int d = p0 + r, tt = o0 + c;
        int idx = bb * 65536 + d * 512 + tt;
        out[idx] += sh[c][r];
    }
}

// ---------------- launch ----------------
extern "C" void kernel_launch(void* const* d_in, const int* in_sizes, int n_in,
                              void* d_out, int out_size) {
    const float* x     = (const float*)d_in[0];
    const int*   ei    = (const int*)d_in[1];
    const float* bn0g  = (const float*)d_in[2];
    const float* bn0b  = (const float*)d_in[3];
    const float* wl    = (const float*)d_in[4];
    const float* wr    = (const float*)d_in[5];
    const float* att   = (const float*)d_in[6];
    const float* bn1g  = (const float*)d_in[8];
    const float* bn1b  = (const float*)d_in[9];
    const float* convw = (const float*)d_in[10];
    const float* bn2g  = (const float*)d_in[12];
    const float* bn2b  = (const float*)d_in[13];
    float* out = (float*)d_out;

    cudaFuncSetAttribute(k_gemm1, cudaFuncAttributeMaxDynamicSharedMemorySize, 81920);
    cudaFuncSetAttribute(k_conv_hmma, cudaFuncAttributeMaxDynamicSharedMemorySize, 118784);

    k_init<<<32, 1024>>>();
    k_hist<<<512, 1024>>>(ei);
    k_bn0p<<<512, 256>>>(x);
    k_scanA<<<32, 1024>>>();
    k_scanB<<<1, 32>>>();
    k_scanC<<<32, 1024>>>();
    k_scatter<<<512, 1024>>>(ei);
    k_fusew<<<1, 256>>>(wl, wr, bn0g, bn0b);
    k_whalf<<<9216, 256>>>(convw);
    k_gemm1<<<512, 256, 81920>>>(x);
    k_gat<<<4096, 256>>>(att);
    k_bn1p<<<256, 256>>>();
    k_bn1f<<<1, 128>>>(bn1g, bn1b);
    k_xn1s<<<4096, 1024>>>(out);
    k_conv_hmma<<<dim3(64, 4), 256, 118784>>>();
    k_bn2<<<512, 256>>>(bn2g, bn2b);
    k_final<<<dim3(4, 16, 64), 256>>>(out);
}

// round 7
// speedup vs baseline: 4.7341x; 1.3825x over previous
#include <cuda_runtime.h>
#include <cuda_fp16.h>
#include <math.h>
#include <stdint.h>

// ---------------- problem constants ----------------
#define NB      64
#define CIN     64
#define TT      512
#define NN      32768
#define DD      128
#define EE      524288
#define ETOT    557056
#define EPSB    1e-5f

typedef unsigned long long ull;

// ---------------- device scratch ----------------
__device__ __align__(16) float g_xl[NN * DD];
__device__ __align__(16) float g_xr[NN * DD];
__device__ __align__(16) float g_gacc[NN * DD];
__device__ __align__(16) float g_y[NB * 512 * 128];
__device__ __align__(16) float g_wf[64 * 256];
__device__ __align__(16) float g_wcs[256];
__device__ __align__(16) __half g_wh[9 * 512 * 512];   // [k][o][i] fp16
__device__ __align__(16) __half g_xh[NB * 128 * 512];  // [b][q][i] fp16
__device__ int g_deg[NN];
__device__ int g_rowptr[NN + 1];
__device__ int g_cursor[NN];
__device__ int g_csrc[ETOT];
__device__ int g_bsum[32];
__device__ int g_boff[32];
__device__ float g_bn0sum[64], g_bn0sq[64];
__device__ float g_bn0s[64], g_bn0t[64];
__device__ float g_bn1sum[128], g_bn1sq[128], g_bn1a[128], g_bn1c[128];
__device__ float g_bn2a[512], g_bn2c[512];

// ---------------- helpers ----------------
__device__ __forceinline__ uint32_t smem_u32(const void* p) {
    uint32_t a;
    asm("{ .reg .u64 t; cvta.to.shared.u64 t, %1; cvt.u32.u64 %0, t; }" : "=r"(a) : "l"(p));
    return a;
}
__device__ __forceinline__ void cpa16(uint32_t dst, const void* src) {
    asm volatile("cp.async.cg.shared.global [%0], [%1], 16;" :: "r"(dst), "l"(src));
}
__device__ __forceinline__ void ldsm4(uint32_t* r, uint32_t addr) {
    asm volatile("ldmatrix.sync.aligned.m8n8.x4.shared.b16 {%0,%1,%2,%3}, [%4];"
                 : "=r"(r[0]), "=r"(r[1]), "=r"(r[2]), "=r"(r[3]) : "r"(addr));
}
__device__ __forceinline__ void mma16816h(float* d, const uint32_t* a, uint32_t b0, uint32_t b1) {
    asm volatile("mma.sync.aligned.m16n8k16.row.col.f32.f16.f16.f32 "
                 "{%0,%1,%2,%3}, {%4,%5,%6,%7}, {%8,%9}, {%0,%1,%2,%3};"
                 : "+f"(d[0]), "+f"(d[1]), "+f"(d[2]), "+f"(d[3])
                 : "r"(a[0]), "r"(a[1]), "r"(a[2]), "r"(a[3]), "r"(b0), "r"(b1));
}

// ---------------- init ----------------
__global__ void k_init() {
    int i = blockIdx.x * 1024 + threadIdx.x;
    g_deg[i] = 1;
    if (i < 128) { g_bn1sum[i] = 0.f; g_bn1sq[i] = 0.f; }
    if (i < 64)  { g_bn0sum[i] = 0.f; g_bn0sq[i] = 0.f; }
}

__global__ void k_hist(const int* __restrict__ ei) {
    int e = blockIdx.x * 1024 + threadIdx.x;
    if (e < EE) atomicAdd(&g_deg[ei[EE + e]], 1);
}

// ---------------- BN0 partial stats ----------------
__global__ void k_bn0p(const float* __restrict__ x) {
    int c = blockIdx.x >> 3;
    int sl = blockIdx.x & 7;
    const float4* base = (const float4*)(x + (size_t)(sl * 8) * 32768 + c * 512);
    int t = threadIdx.x;
    float s = 0.f, q = 0.f;
#pragma unroll
    for (int j = 0; j < 4; j++) {
        int u = t + j * 256;
        int r = u >> 7, col = u & 127;
        float4 v = base[(size_t)r * 8192 + col];
        s += v.x + v.y + v.z + v.w;
        q += v.x * v.x + v.y * v.y + v.z * v.z + v.w * v.w;
    }
    __shared__ float rs[256], rq[256];
    rs[t] = s; rq[t] = q;
    __syncthreads();
    for (int st = 128; st > 0; st >>= 1) {
        if (t < st) { rs[t] += rs[t + st]; rq[t] += rq[t + st]; }
        __syncthreads();
    }
    if (t == 0) { atomicAdd(&g_bn0sum[c], rs[0]); atomicAdd(&g_bn0sq[c], rq[0]); }
}

// ---------------- parallel scan ----------------
__global__ void __launch_bounds__(1024) k_scanA() {
    __shared__ int wsum[32];
    int t = threadIdx.x;
    int n = blockIdx.x * 1024 + t;
    int lane = t & 31, w = t >> 5;
    int d = g_deg[n];
    int incl = d;
#pragma unroll
    for (int off = 1; off < 32; off <<= 1) {
        int v = __shfl_up_sync(0xffffffffu, incl, off);
        if (lane >= off) incl += v;
    }
    if (lane == 31) wsum[w] = incl;
    __syncthreads();
    if (w == 0) {
        int v = wsum[lane];
        int wi = v;
#pragma unroll
        for (int off = 1; off < 32; off <<= 1) {
            int u = __shfl_up_sync(0xffffffffu, wi, off);
            if (lane >= off) wi += u;
        }
        wsum[lane] = wi - v;
        if (lane == 31) g_bsum[blockIdx.x] = wi;
    }
    __syncthreads();
    g_rowptr[n] = incl - d + wsum[w];
}

__global__ void k_scanB() {
    int lane = threadIdx.x;
    int v = g_bsum[lane];
    int s = v;
#pragma unroll
    for (int off = 1; off < 32; off <<= 1) {
        int u = __shfl_up_sync(0xffffffffu, s, off);
        if (lane >= off) s += u;
    }
    g_boff[lane] = s - v;
    if (lane == 31) g_rowptr[NN] = s;
}

__global__ void __launch_bounds__(1024) k_scanC() {
    int n = blockIdx.x * 1024 + threadIdx.x;
    int run = g_rowptr[n] + g_boff[blockIdx.x];
    g_rowptr[n] = run;
    g_cursor[n] = run + 1;
    g_csrc[run] = n;
}

__global__ void k_scatter(const int* __restrict__ ei) {
    int e = blockIdx.x * 1024 + threadIdx.x;
    if (e < EE) {
        int d = ei[EE + e];
        int pos = atomicAdd(&g_cursor[d], 1);
        g_csrc[pos] = ei[e];
    }
}

// ---------------- fuse W_l|W_r + colsums + finalize BN0 ----------------
__global__ void k_fusew(const float* __restrict__ wl, const float* __restrict__ wr,
                        const float* __restrict__ g0, const float* __restrict__ b0) {
    int j = threadIdx.x;
    if (j < 64) {
        float m = g_bn0sum[j] * (1.f / 32768.f);
        float var = g_bn0sq[j] * (1.f / 32768.f) - m * m;
        float a = g0[j] * rsqrtf(var + EPSB);
        g_bn0s[j] = a;
        g_bn0t[j] = b0[j] - m * a;
    }
    float cs = 0.f;
    for (int c = 0; c < 64; c++) {
        float w = (j < 128) ? wl[c * 128 + j] : wr[c * 128 + (j - 128)];
        g_wf[c * 256 + j] = w;
        cs += w;
    }
    g_wcs[j] = cs;
}

// ---------------- GEMM1 ----------------
__global__ void __launch_bounds__(256) k_gemm1(const float* __restrict__ x) {
    extern __shared__ float sm1[];
    float* xs = sm1;
    float* ws = sm1 + 4096;
    int tid = threadIdx.x;
    int r0 = blockIdx.x * 64;
    for (int i = tid; i < 4096; i += 256) xs[i] = x[r0 * 64 + i];
    for (int i = tid; i < 16384; i += 256) ws[i] = g_wf[i];
    __syncthreads();
    int cg = tid & 31, rg = tid >> 5;
    int j0 = cg * 8;
    ull acc[8][4];
#pragma unroll
    for (int rr = 0; rr < 8; rr++)
#pragma unroll
        for (int u = 0; u < 4; u++) acc[rr][u] = 0ull;
    for (int c = 0; c < 64; c++) {
        ull w2[4];
#pragma unroll
        for (int u = 0; u < 4; u++) w2[u] = *(const ull*)&ws[c * 256 + j0 + 2 * u];
#pragma unroll
        for (int rr = 0; rr < 8; rr++) {
            float xv = xs[(rg * 8 + rr) * 64 + c];
            ull xd;
            asm("mov.b64 %0, {%1, %1};" : "=l"(xd) : "f"(xv));
#pragma unroll
            for (int u = 0; u < 4; u++)
                asm("fma.rn.f32x2 %0, %1, %2, %0;" : "+l"(acc[rr][u]) : "l"(xd), "l"(w2[u]));
        }
    }
    float wcs[8];
#pragma unroll
    for (int u = 0; u < 8; u++) wcs[u] = g_wcs[j0 + u];
    float* dst = (j0 < 128) ? g_xl : g_xr;
    int jj = j0 & 127;
#pragma unroll
    for (int rr = 0; rr < 8; rr++) {
        int n = r0 + rg * 8 + rr;
        int cin = (n >> 3) & 63;
        float s = g_bn0s[cin], t = g_bn0t[cin];
#pragma unroll
        for (int u = 0; u < 4; u++) {
            float a0, a1;
            asm("mov.b64 {%0, %1}, %2;" : "=f"(a0), "=f"(a1) : "l"(acc[rr][u]));
            float2 v;
            v.x = s * a0 + t * wcs[2 * u];
            v.y = s * a1 + t * wcs[2 * u + 1];
            *(float2*)&dst[n * 128 + jj + 2 * u] = v;
        }
    }
}

// ---------------- GATv2 gather: warp per node, unroll x4 ----------------
#define GAT_EDGE(AV) do { \
    float hx = AV.x + r.x; hx = fmaxf(hx, 0.2f * hx); \
    float hy = AV.y + r.y; hy = fmaxf(hy, 0.2f * hy); \
    float hz = AV.z + r.z; hz = fmaxf(hz, 0.2f * hz); \
    float hw = AV.w + r.w; hw = fmaxf(hw, 0.2f * hw); \
    float d = hx * av.x + hy * av.y + hz * av.z + hw * av.w; \
    d += __shfl_xor_sync(0xffffffffu, d, 8); \
    d += __shfl_xor_sync(0xffffffffu, d, 4); \
    d += __shfl_xor_sync(0xffffffffu, d, 2); \
    d += __shfl_xor_sync(0xffffffffu, d, 1); \
    float e = __expf(d); \
    z += e; \
    acc.x += e * AV.x; acc.y += e * AV.y; \
    acc.z += e * AV.z; acc.w += e * AV.w; \
} while (0)

__global__ void __launch_bounds__(256) k_gat(const float* __restrict__ att) {
    int n = blockIdx.x * 8 + (threadIdx.x >> 5);
    int lane = threadIdx.x & 31;
    int row = g_rowptr[n];
    int end = g_rowptr[n + 1];
    float4 r = *(const float4*)(g_xr + (size_t)n * 128 + lane * 4);
    float4 av = *(const float4*)(att + lane * 4);
    float4 acc = make_float4(0.f, 0.f, 0.f, 0.f);
    float z = 0.f;
    for (int base = row; base < end; base += 32) {
        int m = end - base;
        if (m > 32) m = 32;
        int s = (lane < m) ? g_csrc[base + lane] : 0;
        int j = 0;
        for (; j + 4 <= m; j += 4) {
            int s0 = __shfl_sync(0xffffffffu, s, j);
            int s1 = __shfl_sync(0xffffffffu, s, j + 1);
            int s2 = __shfl_sync(0xffffffffu, s, j + 2);
            int s3 = __shfl_sync(0xffffffffu, s, j + 3);
            float4 a0 = *(const float4*)(g_xl + (size_t)s0 * 128 + lane * 4);
            float4 a1 = *(const float4*)(g_xl + (size_t)s1 * 128 + lane * 4);
            float4 a2 = *(const float4*)(g_xl + (size_t)s2 * 128 + lane * 4);
            float4 a3 = *(const float4*)(g_xl + (size_t)s3 * 128 + lane * 4);
            GAT_EDGE(a0);
            GAT_EDGE(a1);
            GAT_EDGE(a2);
            GAT_EDGE(a3);
        }
        for (; j < m; j++) {
            int s0 = __shfl_sync(0xffffffffu, s, j);
            float4 a0 = *(const float4*)(g_xl + (size_t)s0 * 128 + lane * 4);
            GAT_EDGE(a0);
        }
    }
    float inv = 1.f / z;
    float4 o = make_float4(acc.x * inv, acc.y * inv, acc.z * inv, acc.w * inv);
    *(float4*)(g_gacc + (size_t)n * 128 + lane * 4) = o;
}

// ---------------- BN1 ----------------
__global__ void k_bn1p() {
    __shared__ float ssum[128], ssq[128];
    int tid = threadIdx.x;
    if (tid < 128) { ssum[tid] = 0.f; ssq[tid] = 0.f; }
    __syncthreads();
    int col = tid & 127;
    float s = 0.f, q = 0.f;
    int base = blockIdx.x * 128;
    for (int r = tid >> 7; r < 128; r += 2) {
        float v = g_gacc[(base + r) * 128 + col];
        s += v; q += v * v;
    }
    atomicAdd(&ssum[col], s);
    atomicAdd(&ssq[col], q);
    __syncthreads();
    if (tid < 128) {
        atomicAdd(&g_bn1sum[tid], ssum[tid]);
        atomicAdd(&g_bn1sq[tid], ssq[tid]);
    }
}

__global__ void k_bn1f(const float* __restrict__ g, const float* __restrict__ b) {
    int j = threadIdx.x;
    float m = g_bn1sum[j] * (1.f / 32768.f);
    float var = g_bn1sq[j] * (1.f / 32768.f) - m * m;
    float a = g[j] * rsqrtf(var + EPSB);
    g_bn1a[j] = a;
    g_bn1c[j] = b[j] - m * a;
}

// ---------------- fused: relu(BN1) -> out + fp16 ----------------
__global__ void k_xn1s(float* __restrict__ out) {
    int i = blockIdx.x * 1024 + threadIdx.x;
    int j = i & 127;
    float v = g_gacc[i] * g_bn1a[j] + g_bn1c[j];
    v = fmaxf(v, 0.f);
    out[i] = v;
    g_xh[i] = __float2half_rn(v);
}

// ---------------- conv weight fp16 ----------------
__global__ void k_whalf(const float* __restrict__ w) {
    int idx = blockIdx.x * 256 + threadIdx.x;   // [k][o][i]
    int i = idx & 511;
    int o = (idx >> 9) & 511;
    int k = idx >> 18;
    g_wh[idx] = __float2half_rn(w[(o * 512 + i) * 9 + k]);
}

// ---------------- conv via mma.sync fp16, 2 batches per CTA ----------------
#define W_STAGE 16384
#define X_BASE  49152
#define X_BUF   34816

__device__ __forceinline__ void fillW(uint32_t sb, int st, int t, int o0, int tid) {
    int kk = t % 9;
    int i0 = (t / 9) * 64;
#pragma unroll
    for (int j = 0; j < 4; j++) {
        int ch = tid + j * 256;
        int r = ch >> 3;
        int c = ch & 7;
        uint32_t dst = sb + st * W_STAGE + r * 128 + ((c * 16) ^ ((r & 7) * 16));
        const __half* src = g_wh + (size_t)(kk * 512 + o0 + r) * 512 + i0 + c * 8;
        cpa16(dst, src);
    }
}

__device__ __forceinline__ void fillX(char* cs, uint32_t sb, int jch, int b0, int tid) {
    int buf = jch & 1;
    int i0 = jch * 64;
#pragma unroll
    for (int jj = 0; jj < 9; jj++) {
        int ch = tid + jj * 256;
        if (ch < 2176) {              // 2 batches x 136 rows x 8 c
            int h = (ch >= 1088) ? 1 : 0;
            int ca = ch - h * 1088;
            int r = ca >> 3;
            int c = ca & 7;
            uint32_t rel = X_BASE + buf * X_BUF + h * 17408 + r * 128 + ((c * 16) ^ ((r & 7) * 16));
            int q = r - 4;
            if ((unsigned)q < 128u) {
                const __half* src = g_xh + (size_t)((b0 + h) * 128 + q) * 512 + i0 + c * 8;
                cpa16(sb + rel, src);
            } else {
                *(uint4*)(cs + rel) = make_uint4(0u, 0u, 0u, 0u);
            }
        }
    }
}

__global__ void __launch_bounds__(256, 1) k_conv_hmma() {
    extern __shared__ char cs[];
    uint32_t sb = smem_u32(cs);
    const int tid = threadIdx.x;
    const int lane = tid & 31;
    const int wid = tid >> 5;
    const int wm = wid & 3;          // 4 M-warps of 32 o-rows
    const int wn = wid >> 2;         // 2 batch halves
    const int b0 = blockIdx.x * 2;
    const int o0 = blockIdx.y * 128;

    float acc[2][16][4];
#pragma unroll
    for (int mt = 0; mt < 2; mt++)
#pragma unroll
        for (int nt = 0; nt < 16; nt++)
#pragma unroll
            for (int u = 0; u < 4; u++) acc[mt][nt][u] = 0.f;

    fillW(sb, 0, 0, o0, tid);
    fillX(cs, sb, 0, b0, tid);
    asm volatile("cp.async.commit_group;" ::: "memory");
    fillW(sb, 1, 1, o0, tid);
    asm volatile("cp.async.commit_group;" ::: "memory");
    fillW(sb, 2, 2, o0, tid);
    asm volatile("cp.async.commit_group;" ::: "memory");

    const int arow = wm * 32 + (lane & 15);
    const int aswz = (arow & 7) * 16;
    const int brow0 = lane & 15;

    for (int t = 0; t < 72; t++) {
        if (t < 70)       asm volatile("cp.async.wait_group 2;" ::: "memory");
        else if (t == 70) asm volatile("cp.async.wait_group 1;" ::: "memory");
        else              asm volatile("cp.async.wait_group 0;" ::: "memory");
        __syncthreads();

        const int st = t % 3;
        const int kk = t % 9;
        const int xb = (t / 9) & 1;
        const uint32_t wbase = sb + st * W_STAGE;
        const uint32_t xbase = sb + X_BASE + xb * X_BUF + wn * 17408;
        const int brow = brow0 + kk;
        const int bswz = (brow & 7) * 16;

#pragma unroll
        for (int s = 0; s < 4; s++) {
            const int c16 = s * 2 + (lane >> 4);
            uint32_t afr[2][4];
#pragma unroll
            for (int mt = 0; mt < 2; mt++) {
                uint32_t addr = wbase + mt * 2048 + arow * 128 + ((c16 * 16) ^ aswz);
                ldsm4(afr[mt], addr);
            }
            uint32_t bfr[8][4];
#pragma unroll
            for (int n16 = 0; n16 < 8; n16++) {
                uint32_t addr = xbase + (brow + n16 * 16) * 128 + ((c16 * 16) ^ bswz);
                ldsm4(bfr[n16], addr);
            }
#pragma unroll
            for (int mt = 0; mt < 2; mt++)
#pragma unroll
                for (int nt = 0; nt < 16; nt++) {
                    const int n16 = nt >> 1, odd = nt & 1;
                    mma16816h(acc[mt][nt], afr[mt], bfr[n16][odd], bfr[n16][odd + 2]);
                }
        }
        __syncthreads();

        const int tf = t + 3;
        if (tf < 72) {
            fillW(sb, tf % 3, tf, o0, tid);
            if (tf % 9 == 0) fillX(cs, sb, tf / 9, b0, tid);
            asm volatile("cp.async.commit_group;" ::: "memory");
        }
    }

    // epilogue -> g_y[b][o][p]
    const int b = b0 + wn;
#pragma unroll
    for (int mt = 0; mt < 2; mt++)
#pragma unroll
        for (int nt = 0; nt < 16; nt++) {
            int o = o0 + wm * 32 + mt * 16 + (lane >> 2);
            int p = nt * 8 + (lane & 3) * 2;
            float2 v0 = make_float2(acc[mt][nt][0], acc[mt][nt][1]);
            float2 v1 = make_float2(acc[mt][nt][2], acc[mt][nt][3]);
            *(float2*)&g_y[((size_t)b * 512 + o) * 128 + p] = v0;
            *(float2*)&g_y[((size_t)b * 512 + o + 8) * 128 + p] = v1;
        }
}

// ---------------- BN2 stats ----------------
__global__ void k_bn2(const float* __restrict__ g, const float* __restrict__ b) {
    int o = blockIdx.x;
    float s = 0.f, q = 0.f;
    for (int idx = threadIdx.x; idx < 8192; idx += 256) {
        int bb = idx >> 7, p = idx & 127;
        float v = g_y[(bb * 512 + o) * 128 + p];
        s += v; q += v * v;
    }
    __shared__ float rs[256], rq[256];
    rs[threadIdx.x] = s; rq[threadIdx.x] = q;
    __syncthreads();
    for (int st = 128; st > 0; st >>= 1) {
        if (threadIdx.x < st) { rs[threadIdx.x] += rs[threadIdx.x + st]; rq[threadIdx.x] += rq[threadIdx.x + st]; }
        __syncthreads();
    }
    if (threadIdx.x == 0) {
        float m = rs[0] * (1.f / 8192.f);
        float var = rq[0] * (1.f / 8192.f) - m * m;
        float a = g[o] * rsqrtf(var + EPSB);
        g_bn2a[o] = a;
        g_bn2c[o] = b[o] - m * a;
    }
}

// ---------------- final ----------------
__global__ void k_final(float* __restrict__ out) {
    __shared__ float sh[32][33];
    int bb = blockIdx.z;
    int o0 = blockIdx.y * 32;
    int p0 = blockIdx.x * 32;
    for (int t = threadIdx.x; t < 1024; t += 256) {
        int r = t >> 5, c = t & 31;
        int o = o0 + r;
        float v = g_y[(bb * 512 + o) * 128 + p0 + c];
        v = v * g_bn2a[o] + g_bn2c[o];
        sh[r][c] = fmaxf(v, 0.f);
    }
    __syncthreads();
    for (int t = threadIdx.x; t < 1024; t += 256) {
        int r = t >> 5, c = t & 31;
        int d = p0 + r, tt = o0 + c;
        int idx = bb * 65536 + d * 512 + tt;
        out[idx] += sh[c][r];
    }
}

// ---------------- launch ----------------
extern "C" void kernel_launch(void* const* d_in, const int* in_sizes, int n_in,
                              void* d_out, int out_size) {
    const float* x     = (const float*)d_in[0];
    const int*   ei    = (const int*)d_in[1];
    const float* bn0g  = (const float*)d_in[2];
    const float* bn0b  = (const float*)d_in[3];
    const float* wl    = (const float*)d_in[4];
    const float* wr    = (const float*)d_in[5];
    const float* att   = (const float*)d_in[6];
    const float* bn1g  = (const float*)d_in[8];
    const float* bn1b  = (const float*)d_in[9];
    const float* convw = (const float*)d_in[10];
    const float* bn2g  = (const float*)d_in[12];
    const float* bn2b  = (const float*)d_in[13];
    float* out = (float*)d_out;

    cudaFuncSetAttribute(k_gemm1, cudaFuncAttributeMaxDynamicSharedMemorySize, 81920);
    cudaFuncSetAttribute(k_conv_hmma, cudaFuncAttributeMaxDynamicSharedMemorySize, 118784);

    k_init<<<32, 1024>>>();
    k_hist<<<512, 1024>>>(ei);
    k_bn0p<<<512, 256>>>(x);
    k_scanA<<<32, 1024>>>();
    k_scanB<<<1, 32>>>();
    k_scanC<<<32, 1024>>>();
    k_scatter<<<512, 1024>>>(ei);
    k_fusew<<<1, 256>>>(wl, wr, bn0g, bn0b);
    k_whalf<<<9216, 256>>>(convw);
    k_gemm1<<<512, 256, 81920>>>(x);
    k_gat<<<4096, 256>>>(att);
    k_bn1p<<<256, 256>>>();
    k_bn1f<<<1, 128>>>(bn1g, bn1b);
    k_xn1s<<<4096, 1024>>>(out);
    k_conv_hmma<<<dim3(32, 4), 256, 118784>>>();
    k_bn2<<<512, 256>>>(bn2g, bn2b);
    k_final<<<dim3(4, 16, 64), 256>>>(out);
}

// round 8
// speedup vs baseline: 4.8239x; 1.0190x over previous
#include <cuda_runtime.h>
#include <cuda_fp16.h>
#include <math.h>
#include <stdint.h>

// ---------------- problem constants ----------------
#define NB      64
#define CIN     64
#define TT      512
#define NN      32768
#define DD      128
#define EE      524288
#define ETOT    557056
#define EPSB    1e-5f

typedef unsigned long long ull;

// ---------------- device scratch ----------------
__device__ __align__(16) float g_xl[NN * DD];
__device__ __align__(16) float g_xr[NN * DD];
__device__ __align__(16) float g_gacc[NN * DD];
__device__ __align__(16) float g_y[NB * 512 * 128];
__device__ __align__(16) float g_wf[64 * 256];
__device__ __align__(16) float g_wcs[256];
__device__ __align__(16) __half g_wh[9 * 512 * 512];   // [k][o][i] fp16
__device__ __align__(16) __half g_xh[NB * 128 * 512];  // [b][q][i] fp16
__device__ int g_deg[NN];
__device__ int g_rowptr[NN + 1];
__device__ int g_cursor[NN];
__device__ int g_csrc[ETOT];
__device__ int g_bsum[32];
__device__ float g_bn0sum[64], g_bn0sq[64];
__device__ float g_bn0s[64], g_bn0t[64];
__device__ float g_bn1sum[128], g_bn1sq[128];
__device__ float g_bn2sum[512], g_bn2sq[512];

// ---------------- helpers ----------------
__device__ __forceinline__ uint32_t smem_u32(const void* p) {
    uint32_t a;
    asm("{ .reg .u64 t; cvta.to.shared.u64 t, %1; cvt.u32.u64 %0, t; }" : "=r"(a) : "l"(p));
    return a;
}
__device__ __forceinline__ void cpa16(uint32_t dst, const void* src) {
    asm volatile("cp.async.cg.shared.global [%0], [%1], 16;" :: "r"(dst), "l"(src));
}
__device__ __forceinline__ void ldsm4(uint32_t* r, uint32_t addr) {
    asm volatile("ldmatrix.sync.aligned.m8n8.x4.shared.b16 {%0,%1,%2,%3}, [%4];"
                 : "=r"(r[0]), "=r"(r[1]), "=r"(r[2]), "=r"(r[3]) : "r"(addr));
}
__device__ __forceinline__ void mma16816h(float* d, const uint32_t* a, uint32_t b0, uint32_t b1) {
    asm volatile("mma.sync.aligned.m16n8k16.row.col.f32.f16.f16.f32 "
                 "{%0,%1,%2,%3}, {%4,%5,%6,%7}, {%8,%9}, {%0,%1,%2,%3};"
                 : "+f"(d[0]), "+f"(d[1]), "+f"(d[2]), "+f"(d[3])
                 : "r"(a[0]), "r"(a[1]), "r"(a[2]), "r"(a[3]), "r"(b0), "r"(b1));
}

// ---------------- init ----------------
__global__ void k_init() {
    int i = blockIdx.x * 1024 + threadIdx.x;
    g_deg[i] = 1;
    if (i < 512) { g_bn2sum[i] = 0.f; g_bn2sq[i] = 0.f; }
    if (i < 128) { g_bn1sum[i] = 0.f; g_bn1sq[i] = 0.f; }
    if (i < 64)  { g_bn0sum[i] = 0.f; g_bn0sq[i] = 0.f; }
}

__global__ void k_hist(const int* __restrict__ ei) {
    int e = blockIdx.x * 1024 + threadIdx.x;
    if (e < EE) atomicAdd(&g_deg[ei[EE + e]], 1);
}

// ---------------- BN0 partial stats ----------------
__global__ void k_bn0p(const float* __restrict__ x) {
    int c = blockIdx.x >> 3;
    int sl = blockIdx.x & 7;
    const float4* base = (const float4*)(x + (size_t)(sl * 8) * 32768 + c * 512);
    int t = threadIdx.x;
    float s = 0.f, q = 0.f;
#pragma unroll
    for (int j = 0; j < 4; j++) {
        int u = t + j * 256;
        int r = u >> 7, col = u & 127;
        float4 v = base[(size_t)r * 8192 + col];
        s += v.x + v.y + v.z + v.w;
        q += v.x * v.x + v.y * v.y + v.z * v.z + v.w * v.w;
    }
    __shared__ float rs[256], rq[256];
    rs[t] = s; rq[t] = q;
    __syncthreads();
    for (int st = 128; st > 0; st >>= 1) {
        if (t < st) { rs[t] += rs[t + st]; rq[t] += rq[t + st]; }
        __syncthreads();
    }
    if (t == 0) { atomicAdd(&g_bn0sum[c], rs[0]); atomicAdd(&g_bn0sq[c], rq[0]); }
}

// ---------------- parallel scan ----------------
__global__ void __launch_bounds__(1024) k_scanA() {
    __shared__ int wsum[32];
    int t = threadIdx.x;
    int n = blockIdx.x * 1024 + t;
    int lane = t & 31, w = t >> 5;
    int d = g_deg[n];
    int incl = d;
#pragma unroll
    for (int off = 1; off < 32; off <<= 1) {
        int v = __shfl_up_sync(0xffffffffu, incl, off);
        if (lane >= off) incl += v;
    }
    if (lane == 31) wsum[w] = incl;
    __syncthreads();
    if (w == 0) {
        int v = wsum[lane];
        int wi = v;
#pragma unroll
        for (int off = 1; off < 32; off <<= 1) {
            int u = __shfl_up_sync(0xffffffffu, wi, off);
            if (lane >= off) wi += u;
        }
        wsum[lane] = wi - v;
        if (lane == 31) g_bsum[blockIdx.x] = wi;
    }
    __syncthreads();
    g_rowptr[n] = incl - d + wsum[w];
}

// scanC with fused scanB: warp 0 re-scans the 32 block sums
__global__ void __launch_bounds__(1024) k_scanC() {
    __shared__ int boff;
    int t = threadIdx.x;
    if (t < 32) {
        int v = g_bsum[t];
        int s = v;
#pragma unroll
        for (int off = 1; off < 32; off <<= 1) {
            int u = __shfl_up_sync(0xffffffffu, s, off);
            if (t >= off) s += u;
        }
        if (t == (int)blockIdx.x) boff = s - v;
        if (t == 31 && blockIdx.x == 31) g_rowptr[NN] = s;
    }
    __syncthreads();
    int n = blockIdx.x * 1024 + t;
    int run = g_rowptr[n] + boff;
    g_rowptr[n] = run;
    g_cursor[n] = run + 1;
    g_csrc[run] = n;
}

__global__ void k_scatter(const int* __restrict__ ei) {
    int e = blockIdx.x * 1024 + threadIdx.x;
    if (e < EE) {
        int d = ei[EE + e];
        int pos = atomicAdd(&g_cursor[d], 1);
        g_csrc[pos] = ei[e];
    }
}

// ---------------- fuse W_l|W_r + colsums + finalize BN0 ----------------
__global__ void k_fusew(const float* __restrict__ wl, const float* __restrict__ wr,
                        const float* __restrict__ g0, const float* __restrict__ b0) {
    int j = threadIdx.x;
    if (j < 64) {
        float m = g_bn0sum[j] * (1.f / 32768.f);
        float var = g_bn0sq[j] * (1.f / 32768.f) - m * m;
        float a = g0[j] * rsqrtf(var + EPSB);
        g_bn0s[j] = a;
        g_bn0t[j] = b0[j] - m * a;
    }
    float cs = 0.f;
    for (int c = 0; c < 64; c++) {
        float w = (j < 128) ? wl[c * 128 + j] : wr[c * 128 + (j - 128)];
        g_wf[c * 256 + j] = w;
        cs += w;
    }
    g_wcs[j] = cs;
}

// ---------------- GEMM1 ----------------
__global__ void __launch_bounds__(256) k_gemm1(const float* __restrict__ x) {
    extern __shared__ float sm1[];
    float* xs = sm1;
    float* ws = sm1 + 4096;
    int tid = threadIdx.x;
    int r0 = blockIdx.x * 64;
    for (int i = tid; i < 4096; i += 256) xs[i] = x[r0 * 64 + i];
    for (int i = tid; i < 16384; i += 256) ws[i] = g_wf[i];
    __syncthreads();
    int cg = tid & 31, rg = tid >> 5;
    int j0 = cg * 8;
    ull acc[8][4];
#pragma unroll
    for (int rr = 0; rr < 8; rr++)
#pragma unroll
        for (int u = 0; u < 4; u++) acc[rr][u] = 0ull;
    for (int c = 0; c < 64; c++) {
        ull w2[4];
#pragma unroll
        for (int u = 0; u < 4; u++) w2[u] = *(const ull*)&ws[c * 256 + j0 + 2 * u];
#pragma unroll
        for (int rr = 0; rr < 8; rr++) {
            float xv = xs[(rg * 8 + rr) * 64 + c];
            ull xd;
            asm("mov.b64 %0, {%1, %1};" : "=l"(xd) : "f"(xv));
#pragma unroll
            for (int u = 0; u < 4; u++)
                asm("fma.rn.f32x2 %0, %1, %2, %0;" : "+l"(acc[rr][u]) : "l"(xd), "l"(w2[u]));
        }
    }
    float wcs[8];
#pragma unroll
    for (int u = 0; u < 8; u++) wcs[u] = g_wcs[j0 + u];
    float* dst = (j0 < 128) ? g_xl : g_xr;
    int jj = j0 & 127;
#pragma unroll
    for (int rr = 0; rr < 8; rr++) {
        int n = r0 + rg * 8 + rr;
        int cin = (n >> 3) & 63;
        float s = g_bn0s[cin], t = g_bn0t[cin];
#pragma unroll
        for (int u = 0; u < 4; u++) {
            float a0, a1;
            asm("mov.b64 {%0, %1}, %2;" : "=f"(a0), "=f"(a1) : "l"(acc[rr][u]));
            float2 v;
            v.x = s * a0 + t * wcs[2 * u];
            v.y = s * a1 + t * wcs[2 * u + 1];
            *(float2*)&dst[n * 128 + jj + 2 * u] = v;
        }
    }
}

// ---------------- GATv2 gather + fused BN1 stats ----------------
#define GAT_EDGE(AV) do { \
    float hx = AV.x + r.x; hx = fmaxf(hx, 0.2f * hx); \
    float hy = AV.y + r.y; hy = fmaxf(hy, 0.2f * hy); \
    float hz = AV.z + r.z; hz = fmaxf(hz, 0.2f * hz); \
    float hw = AV.w + r.w; hw = fmaxf(hw, 0.2f * hw); \
    float d = hx * av.x + hy * av.y + hz * av.z + hw * av.w; \
    d += __shfl_xor_sync(0xffffffffu, d, 8); \
    d += __shfl_xor_sync(0xffffffffu, d, 4); \
    d += __shfl_xor_sync(0xffffffffu, d, 2); \
    d += __shfl_xor_sync(0xffffffffu, d, 1); \
    float e = __expf(d); \
    z += e; \
    acc.x += e * AV.x; acc.y += e * AV.y; \
    acc.z += e * AV.z; acc.w += e * AV.w; \
} while (0)

__global__ void __launch_bounds__(256) k_gat(const float* __restrict__ att) {
    __shared__ float ssum[128], ssq[128];
    int tid = threadIdx.x;
    if (tid < 128) { ssum[tid] = 0.f; ssq[tid] = 0.f; }
    __syncthreads();
    int n = blockIdx.x * 8 + (tid >> 5);
    int lane = tid & 31;
    int row = g_rowptr[n];
    int end = g_rowptr[n + 1];
    float4 r = *(const float4*)(g_xr + (size_t)n * 128 + lane * 4);
    float4 av = *(const float4*)(att + lane * 4);
    float4 acc = make_float4(0.f, 0.f, 0.f, 0.f);
    float z = 0.f;
    for (int base = row; base < end; base += 32) {
        int m = end - base;
        if (m > 32) m = 32;
        int s = (lane < m) ? g_csrc[base + lane] : 0;
        int j = 0;
        for (; j + 4 <= m; j += 4) {
            int s0 = __shfl_sync(0xffffffffu, s, j);
            int s1 = __shfl_sync(0xffffffffu, s, j + 1);
            int s2 = __shfl_sync(0xffffffffu, s, j + 2);
            int s3 = __shfl_sync(0xffffffffu, s, j + 3);
            float4 a0 = *(const float4*)(g_xl + (size_t)s0 * 128 + lane * 4);
            float4 a1 = *(const float4*)(g_xl + (size_t)s1 * 128 + lane * 4);
            float4 a2 = *(const float4*)(g_xl + (size_t)s2 * 128 + lane * 4);
            float4 a3 = *(const float4*)(g_xl + (size_t)s3 * 128 + lane * 4);
            GAT_EDGE(a0);
            GAT_EDGE(a1);
            GAT_EDGE(a2);
            GAT_EDGE(a3);
        }
        for (; j < m; j++) {
            int s0 = __shfl_sync(0xffffffffu, s, j);
            float4 a0 = *(const float4*)(g_xl + (size_t)s0 * 128 + lane * 4);
            GAT_EDGE(a0);
        }
    }
    float inv = 1.f / z;
    float4 o = make_float4(acc.x * inv, acc.y * inv, acc.z * inv, acc.w * inv);
    *(float4*)(g_gacc + (size_t)n * 128 + lane * 4) = o;
    // BN1 partial stats
    atomicAdd(&ssum[lane * 4 + 0], o.x);
    atomicAdd(&ssum[lane * 4 + 1], o.y);
    atomicAdd(&ssum[lane * 4 + 2], o.z);
    atomicAdd(&ssum[lane * 4 + 3], o.w);
    atomicAdd(&ssq[lane * 4 + 0], o.x * o.x);
    atomicAdd(&ssq[lane * 4 + 1], o.y * o.y);
    atomicAdd(&ssq[lane * 4 + 2], o.z * o.z);
    atomicAdd(&ssq[lane * 4 + 3], o.w * o.w);
    __syncthreads();
    if (tid < 128) {
        atomicAdd(&g_bn1sum[tid], ssum[tid]);
        atomicAdd(&g_bn1sq[tid], ssq[tid]);
    }
}

// ---------------- fused: relu(BN1) -> out + fp16 (inline coefficients) ----------------
__global__ void __launch_bounds__(1024) k_xn1s(float* __restrict__ out,
                                               const float* __restrict__ g1,
                                               const float* __restrict__ b1) {
    __shared__ float sa[128], sc[128];
    int tid = threadIdx.x;
    if (tid < 128) {
        float m = g_bn1sum[tid] * (1.f / 32768.f);
        float var = g_bn1sq[tid] * (1.f / 32768.f) - m * m;
        float a = g1[tid] * rsqrtf(var + EPSB);
        sa[tid] = a;
        sc[tid] = b1[tid] - m * a;
    }
    __syncthreads();
    int i = blockIdx.x * 1024 + tid;
    int j = tid & 127;
    float v = g_gacc[i] * sa[j] + sc[j];
    v = fmaxf(v, 0.f);
    out[i] = v;
    g_xh[i] = __float2half_rn(v);
}

// ---------------- conv weight fp16 ----------------
__global__ void k_whalf(const float* __restrict__ w) {
    int idx = blockIdx.x * 256 + threadIdx.x;   // [k][o][i]
    int i = idx & 511;
    int o = (idx >> 9) & 511;
    int k = idx >> 18;
    g_wh[idx] = __float2half_rn(w[(o * 512 + i) * 9 + k]);
}

// ---------------- conv via mma.sync fp16, 2 batches per CTA + BN2 stats ----------------
#define W_STAGE 16384
#define X_BASE  49152
#define X_BUF   34816

__device__ __forceinline__ void fillW(uint32_t sb, int st, int t, int o0, int tid) {
    int kk = t % 9;
    int i0 = (t / 9) * 64;
#pragma unroll
    for (int j = 0; j < 4; j++) {
        int ch = tid + j * 256;
        int r = ch >> 3;
        int c = ch & 7;
        uint32_t dst = sb + st * W_STAGE + r * 128 + ((c * 16) ^ ((r & 7) * 16));
        const __half* src = g_wh + (size_t)(kk * 512 + o0 + r) * 512 + i0 + c * 8;
        cpa16(dst, src);
    }
}

__device__ __forceinline__ void fillX(char* cs, uint32_t sb, int jch, int b0, int tid) {
    int buf = jch & 1;
    int i0 = jch * 64;
#pragma unroll
    for (int jj = 0; jj < 9; jj++) {
        int ch = tid + jj * 256;
        if (ch < 2176) {
            int h = (ch >= 1088) ? 1 : 0;
            int ca = ch - h * 1088;
            int r = ca >> 3;
            int c = ca & 7;
            uint32_t rel = X_BASE + buf * X_BUF + h * 17408 + r * 128 + ((c * 16) ^ ((r & 7) * 16));
            int q = r - 4;
            if ((unsigned)q < 128u) {
                const __half* src = g_xh + (size_t)((b0 + h) * 128 + q) * 512 + i0 + c * 8;
                cpa16(sb + rel, src);
            } else {
                *(uint4*)(cs + rel) = make_uint4(0u, 0u, 0u, 0u);
            }
        }
    }
}

__global__ void __launch_bounds__(256, 1) k_conv_hmma() {
    extern __shared__ char cs[];
    uint32_t sb = smem_u32(cs);
    const int tid = threadIdx.x;
    const int lane = tid & 31;
    const int wid = tid >> 5;
    const int wm = wid & 3;
    const int wn = wid >> 2;
    const int b0 = blockIdx.x * 2;
    const int o0 = blockIdx.y * 128;

    float acc[2][16][4];
#pragma unroll
    for (int mt = 0; mt < 2; mt++)
#pragma unroll
        for (int nt = 0; nt < 16; nt++)
#pragma unroll
            for (int u = 0; u < 4; u++) acc[mt][nt][u] = 0.f;

    fillW(sb, 0, 0, o0, tid);
    fillX(cs, sb, 0, b0, tid);
    asm volatile("cp.async.commit_group;" ::: "memory");
    fillW(sb, 1, 1, o0, tid);
    asm volatile("cp.async.commit_group;" ::: "memory");
    fillW(sb, 2, 2, o0, tid);
    asm volatile("cp.async.commit_group;" ::: "memory");

    const int arow = wm * 32 + (lane & 15);
    const int aswz = (arow & 7) * 16;
    const int brow0 = lane & 15;

    for (int t = 0; t < 72; t++) {
        if (t < 70)       asm volatile("cp.async.wait_group 2;" ::: "memory");
        else if (t == 70) asm volatile("cp.async.wait_group 1;" ::: "memory");
        else              asm volatile("cp.async.wait_group 0;" ::: "memory");
        __syncthreads();

        const int st = t % 3;
        const int kk = t % 9;
        const int xb = (t / 9) & 1;
        const uint32_t wbase = sb + st * W_STAGE;
        const uint32_t xbase = sb + X_BASE + xb * X_BUF + wn * 17408;
        const int brow = brow0 + kk;
        const int bswz = (brow & 7) * 16;

#pragma unroll
        for (int s = 0; s < 4; s++) {
            const int c16 = s * 2 + (lane >> 4);
            uint32_t afr[2][4];
#pragma unroll
            for (int mt = 0; mt < 2; mt++) {
                uint32_t addr = wbase + mt * 2048 + arow * 128 + ((c16 * 16) ^ aswz);
                ldsm4(afr[mt], addr);
            }
            uint32_t bfr[8][4];
#pragma unroll
            for (int n16 = 0; n16 < 8; n16++) {
                uint32_t addr = xbase + (brow + n16 * 16) * 128 + ((c16 * 16) ^ bswz);
                ldsm4(bfr[n16], addr);
            }
#pragma unroll
            for (int mt = 0; mt < 2; mt++)
#pragma unroll
                for (int nt = 0; nt < 16; nt++) {
                    const int n16 = nt >> 1, odd = nt & 1;
                    mma16816h(acc[mt][nt], afr[mt], bfr[n16][odd], bfr[n16][odd + 2]);
                }
        }
        __syncthreads();

        const int tf = t + 3;
        if (tf < 72) {
            fillW(sb, tf % 3, tf, o0, tid);
            if (tf % 9 == 0) fillX(cs, sb, tf / 9, b0, tid);
            asm volatile("cp.async.commit_group;" ::: "memory");
        }
    }

    // epilogue -> g_y[b][o][p] + BN2 partial stats
    const int b = b0 + wn;
#pragma unroll
    for (int mt = 0; mt < 2; mt++) {
        float slo = 0.f, qlo = 0.f, shi = 0.f, qhi = 0.f;
#pragma unroll
        for (int nt = 0; nt < 16; nt++) {
            int o = o0 + wm * 32 + mt * 16 + (lane >> 2);
            int p = nt * 8 + (lane & 3) * 2;
            float2 v0 = make_float2(acc[mt][nt][0], acc[mt][nt][1]);
            float2 v1 = make_float2(acc[mt][nt][2], acc[mt][nt][3]);
            *(float2*)&g_y[((size_t)b * 512 + o) * 128 + p] = v0;
            *(float2*)&g_y[((size_t)b * 512 + o + 8) * 128 + p] = v1;
            slo += v0.x + v0.y; qlo += v0.x * v0.x + v0.y * v0.y;
            shi += v1.x + v1.y; qhi += v1.x * v1.x + v1.y * v1.y;
        }
        // reduce over the 4 lanes of the quad (same o)
#pragma unroll
        for (int m = 1; m <= 2; m <<= 1) {
            slo += __shfl_xor_sync(0xffffffffu, slo, m);
            qlo += __shfl_xor_sync(0xffffffffu, qlo, m);
            shi += __shfl_xor_sync(0xffffffffu, shi, m);
            qhi += __shfl_xor_sync(0xffffffffu, qhi, m);
        }
        if ((lane & 3) == 0) {
            int o = o0 + wm * 32 + mt * 16 + (lane >> 2);
            atomicAdd(&g_bn2sum[o], slo);
            atomicAdd(&g_bn2sq[o], qlo);
            atomicAdd(&g_bn2sum[o + 8], shi);
            atomicAdd(&g_bn2sq[o + 8], qhi);
        }
    }
}

// ---------------- final (inline BN2 coefficients) ----------------
__global__ void k_final(float* __restrict__ out,
                        const float* __restrict__ g2, const float* __restrict__ b2) {
    __shared__ float sh[32][33];
    __shared__ float sa[32], sc[32];
    int bb = blockIdx.z;
    int o0 = blockIdx.y * 32;
    int p0 = blockIdx.x * 32;
    int tid = threadIdx.x;
    if (tid < 32) {
        int o = o0 + tid;
        float m = g_bn2sum[o] * (1.f / 8192.f);
        float var = g_bn2sq[o] * (1.f / 8192.f) - m * m;
        float a = g2[o] * rsqrtf(var + EPSB);
        sa[tid] = a;
        sc[tid] = b2[o] - m * a;
    }
    __syncthreads();
    for (int t = tid; t < 1024; t += 256) {
        int r = t >> 5, c = t & 31;
        int o = o0 + r;
        float v = g_y[(bb * 512 + o) * 128 + p0 + c];
        v = v * sa[r] + sc[r];
        sh[r][c] = fmaxf(v, 0.f);
    }
    __syncthreads();
    for (int t = tid; t < 1024; t += 256) {
        int r = t >> 5, c = t & 31;
        int d = p0 + r, tt = o0 + c;
        int idx = bb * 65536 + d * 512 + tt;
        out[idx] += sh[c][r];
    }
}

// ---------------- launch ----------------
extern "C" void kernel_launch(void* const* d_in, const int* in_sizes, int n_in,
                              void* d_out, int out_size) {
    const float* x     = (const float*)d_in[0];
    const int*   ei    = (const int*)d_in[1];
    const float* bn0g  = (const float*)d_in[2];
    const float* bn0b  = (const float*)d_in[3];
    const float* wl    = (const float*)d_in[4];
    const float* wr    = (const float*)d_in[5];
    const float* att   = (const float*)d_in[6];
    const float* bn1g  = (const float*)d_in[8];
    const float* bn1b  = (const float*)d_in[9];
    const float* convw = (const float*)d_in[10];
    const float* bn2g  = (const float*)d_in[12];
    const float* bn2b  = (const float*)d_in[13];
    float* out = (float*)d_out;

    cudaFuncSetAttribute(k_gemm1, cudaFuncAttributeMaxDynamicSharedMemorySize, 81920);
    cudaFuncSetAttribute(k_conv_hmma, cudaFuncAttributeMaxDynamicSharedMemorySize, 118784);

    k_init<<<32, 1024>>>();
    k_hist<<<512, 1024>>>(ei);
    k_bn0p<<<512, 256>>>(x);
    k_scanA<<<32, 1024>>>();
    k_scanC<<<32, 1024>>>();
    k_scatter<<<512, 1024>>>(ei);
    k_fusew<<<1, 256>>>(wl, wr, bn0g, bn0b);
    k_whalf<<<9216, 256>>>(convw);
    k_gemm1<<<512, 256, 81920>>>(x);
    k_gat<<<4096, 256>>>(att);
    k_xn1s<<<4096, 1024>>>(out, bn1g, bn1b);
    k_conv_hmma<<<dim3(32, 4), 256, 118784>>>();
    k_final<<<dim3(4, 16, 64), 256>>>(out, bn2g, bn2b);
}